// round 6
// baseline (speedup 1.0000x reference)
#include <cuda_runtime.h>
#include <cstdint>

#define BSZ 8
#define NPT 1024
#define KNN 20
#define NEG 0.2f
#define EPSB 1e-5f
#define NPTS_TOT (BSZ*NPT)
#define FLTMAX 3.402823466e38f

// ------------------------- scratch (device globals; no allocs) -------------
__device__ float  g_X0 [BSZ*NPT*3];
__device__ float  g_XX [BSZ*NPT];
__device__ float  g_PD [BSZ*NPT*NPT];        // 32 MB pairwise scores
__device__ int    g_IDX[BSZ*NPT*KNN];
__device__ float  g_YMX[BSZ*NPT*256];
__device__ float  g_YMN[BSZ*NPT*256];
__device__ float  g_CAT[BSZ*NPT*512];        // x1|x2|x3|x4 per point row
__device__ float  g_Y5 [BSZ*NPT*1024];       // 32 MB conv5 output
__device__ float  g_WC [512*128];            // L4 combined [W1; W2-W1]
__device__ float  g_PQ [BSZ*NPT*512];        // L4 [P | Q] per point (16 MB)
__device__ double g_SUM[1024];
__device__ double g_SQS[1024];
__device__ float  g_M  [1024];
__device__ float  g_RS [1024];
__device__ float  g_FEAT[BSZ*2048];
__device__ float  g_H1 [BSZ*512];
__device__ float  g_H2 [BSZ*256];

// ------------------------- small utility kernels ---------------------------
__global__ void transpose_x_kernel(const float* __restrict__ x, float* __restrict__ X0) {
    int i = blockIdx.x * blockDim.x + threadIdx.x;
    if (i < BSZ*NPT*3) {
        int b = i / (NPT*3); int rest = i % (NPT*3);
        int n = rest / 3, c = rest % 3;
        X0[i] = x[((size_t)b*3 + c)*NPT + n];
    }
}

// xx[n] = sum_c x[n,c]^2  — square rounded, then ascending adds (NO fma)
__global__ void rownorm_kernel(const float* __restrict__ X, int ld, int Cin,
                               float* __restrict__ xx) {
    int pt = blockIdx.x * blockDim.x + threadIdx.x;
    if (pt < NPTS_TOT) {
        const float* r = X + (size_t)pt * ld;
        float s = 0.f;
        for (int c = 0; c < Cin; c++) {
            float v = r[c];
            s = __fadd_rn(s, __fmul_rn(v, v));
        }
        xx[pt] = s;
    }
}

__global__ void zero_stats_kernel(double* a, double* b) {
    int i = blockIdx.x * blockDim.x + threadIdx.x;
    if (i < 1024) { a[i] = 0.0; b[i] = 0.0; }
}

// L4 combined weights: WC[o] = W1[o]; WC[Cout+o] = W2[o]-W1[o]
__global__ void wcomb_kernel(const float* __restrict__ W, int Cin, int Cout,
                             float* __restrict__ WC) {
    int i = blockIdx.x * blockDim.x + threadIdx.x;
    if (i < 2*Cout*Cin) {
        int o = i / Cin, c = i % Cin;
        if (o < Cout) WC[i] = W[(size_t)o*(2*Cin) + c];
        else {
            int oo = o - Cout;
            WC[i] = __fsub_rn(W[(size_t)oo*(2*Cin) + Cin + c],
                              W[(size_t)oo*(2*Cin) + c]);
        }
    }
}

// From fp64 sums: m = fp32(mean); v = two-pass-style variance; rs = rsqrtf(v+eps)
__global__ void bnfin_kernel(const double* __restrict__ sum, const double* __restrict__ sqs,
                             double cnt, int C,
                             float* __restrict__ M, float* __restrict__ RS) {
    int o = blockIdx.x * blockDim.x + threadIdx.x;
    if (o < C) {
        double mu = sum[o] / cnt;
        float m = (float)mu;
        double vd = sqs[o]/cnt - 2.0*(double)m*mu + (double)m*(double)m;
        float v = (float)vd;
        M[o]  = m;
        RS[o] = rsqrtf(__fadd_rn(v, EPSB));
    }
}

// ------------------------- tiled fp32 GEMM (128x64, 256 thr, 8x4) ----------
// C[b,i,j] = sum_c X[b,i,c]*W[j,c], ascending-K single-accumulator fma chain.
__global__ void gemm_xw_kernel(const float* __restrict__ X, int ldx, int Cin,
                               const float* __restrict__ W,
                               float* __restrict__ out, int ldo) {
    int b  = blockIdx.z;
    int i0 = blockIdx.x * 128;
    int j0 = blockIdx.y * 64;
    __shared__ float As[16][132];
    __shared__ float Bs[16][68];
    int tid = threadIdx.x, tx = tid % 16, ty = tid / 16;
    float acc[8][4] = {};
    const float* Xb = X + (size_t)b * NPT * ldx;
    for (int k0 = 0; k0 < Cin; k0 += 16) {
        #pragma unroll
        for (int l = tid; l < 128*16; l += 256) {
            int r = l >> 4, c = l & 15; int kk = k0 + c;
            As[c][r] = (kk < Cin) ? Xb[(size_t)(i0 + r)*ldx + kk] : 0.f;
        }
        #pragma unroll
        for (int l = tid; l < 64*16; l += 256) {
            int r = l >> 4, c = l & 15; int kk = k0 + c;
            Bs[c][r] = (kk < Cin) ? W[(size_t)(j0 + r)*Cin + kk] : 0.f;
        }
        __syncthreads();
        #pragma unroll
        for (int kk = 0; kk < 16; kk++) {
            float4 a0 = *(const float4*)&As[kk][ty*8];
            float4 a1 = *(const float4*)&As[kk][ty*8 + 4];
            float4 bv = *(const float4*)&Bs[kk][tx*4];
            float a[8] = {a0.x,a0.y,a0.z,a0.w,a1.x,a1.y,a1.z,a1.w};
            float bb[4] = {bv.x,bv.y,bv.z,bv.w};
            #pragma unroll
            for (int i = 0; i < 8; i++)
                #pragma unroll
                for (int j = 0; j < 4; j++)
                    acc[i][j] = __fmaf_rn(a[i], bb[j], acc[i][j]);
        }
        __syncthreads();
    }
    float* outb = out + (size_t)b * NPT * ldo;
    #pragma unroll
    for (int i = 0; i < 8; i++) {
        float4 v = make_float4(acc[i][0], acc[i][1], acc[i][2], acc[i][3]);
        *(float4*)&outb[(size_t)(i0 + ty*8 + i)*ldo + (j0 + tx*4)] = v;
    }
}

// pd[b,i,j] = (-xx[j] - (-2*dot_ij)) - xx[i], dot via ascending fma (exact fp32)
__global__ void gram_kernel(const float* __restrict__ X, int ldx, int Cin,
                            const float* __restrict__ xx, float* __restrict__ S) {
    int b  = blockIdx.z;
    int i0 = blockIdx.x * 128;
    int j0 = blockIdx.y * 64;
    __shared__ float As[16][132];
    __shared__ float Bs[16][68];
    int tid = threadIdx.x, tx = tid % 16, ty = tid / 16;
    float acc[8][4] = {};
    const float* Xb = X + (size_t)b * NPT * ldx;
    for (int k0 = 0; k0 < Cin; k0 += 16) {
        #pragma unroll
        for (int l = tid; l < 128*16; l += 256) {
            int r = l >> 4, c = l & 15; int kk = k0 + c;
            As[c][r] = (kk < Cin) ? Xb[(size_t)(i0 + r)*ldx + kk] : 0.f;
        }
        #pragma unroll
        for (int l = tid; l < 64*16; l += 256) {
            int r = l >> 4, c = l & 15; int kk = k0 + c;
            Bs[c][r] = (kk < Cin) ? Xb[(size_t)(j0 + r)*ldx + kk] : 0.f;
        }
        __syncthreads();
        #pragma unroll
        for (int kk = 0; kk < 16; kk++) {
            float4 a0 = *(const float4*)&As[kk][ty*8];
            float4 a1 = *(const float4*)&As[kk][ty*8 + 4];
            float4 bv = *(const float4*)&Bs[kk][tx*4];
            float a[8] = {a0.x,a0.y,a0.z,a0.w,a1.x,a1.y,a1.z,a1.w};
            float bb[4] = {bv.x,bv.y,bv.z,bv.w};
            #pragma unroll
            for (int i = 0; i < 8; i++)
                #pragma unroll
                for (int j = 0; j < 4; j++)
                    acc[i][j] = __fmaf_rn(a[i], bb[j], acc[i][j]);
        }
        __syncthreads();
    }
    float* Sb = S + (size_t)b * NPT * NPT;
    const float* xxb = xx + (size_t)b * NPT;
    float4 xj = *(const float4*)&xxb[j0 + tx*4];
    float xjv[4] = {xj.x, xj.y, xj.z, xj.w};
    #pragma unroll
    for (int i = 0; i < 8; i++) {
        float xi = xxb[i0 + ty*8 + i];
        float e[4];
        #pragma unroll
        for (int j = 0; j < 4; j++) {
            float inner = __fmul_rn(-2.f, acc[i][j]);
            float t1 = __fsub_rn(-xjv[j], inner);
            e[j] = __fsub_rn(t1, xi);
        }
        *(float4*)&Sb[(size_t)(i0 + ty*8 + i)*NPT + (j0 + tx*4)]
            = make_float4(e[0], e[1], e[2], e[3]);
    }
}

// ------------------------- top-k (warp per row, register-resident) ----------
// jax.lax.top_k semantics: values descending, ties broken by lowest index.
__global__ void topk_kernel(const float* __restrict__ S, int* __restrict__ idxout) {
    int gwarp = (blockIdx.x * blockDim.x + threadIdx.x) >> 5;
    int lane  = threadIdx.x & 31;
    if (gwarp >= NPTS_TOT) return;
    const float* row = S + (size_t)gwarp * NPT;

    float v[32];
    #pragma unroll
    for (int j = 0; j < 32; j++) v[j] = row[lane + (j << 5)];

    int* outp = idxout + (size_t)gwarp * KNN;
    for (int k = 0; k < KNN; k++) {
        float bm = v[0]; int bj = 0;
        #pragma unroll
        for (int j = 1; j < 32; j++)
            if (v[j] > bm) { bm = v[j]; bj = j; }
        float wv = bm;
        int   wm = lane + (bj << 5);
        #pragma unroll
        for (int off = 16; off > 0; off >>= 1) {
            float ov = __shfl_xor_sync(0xffffffff, wv, off);
            int   om = __shfl_xor_sync(0xffffffff, wm, off);
            if (ov > wv || (ov == wv && om < wm)) { wv = ov; wm = om; }
        }
        if (lane == 0) outp[k] = wm;
        if ((wm & 31) == lane) {
            int jj = wm >> 5;
            #pragma unroll
            for (int j = 0; j < 32; j++)
                if (j == jj) v[j] = -FLTMAX;
        }
    }
}

// ------------------------- per-edge EXACT fp32 EdgeConv (L1-L3) -------------
// 256 threads = 8 warps; warp w owns point pt0+w (its 20 edges).
// lane: egsub = lane>>3 (4 groups of 5 edges), og = lane&7 (8 outs each).
// Same ascending-fma chain per (edge,out) as before -> bit-identical features.
__global__ void edgeconv_kernel(const float* __restrict__ X, int ld, int Cin, int Cout,
                                const float* __restrict__ W,
                                const int* __restrict__ idx,
                                float* __restrict__ ymax, float* __restrict__ ymin,
                                double* __restrict__ chanSum, double* __restrict__ chanSqs) {
    __shared__ float  As[16][164];
    __shared__ float  Bs[16][68];
    __shared__ double rs_sum[8][64], rs_sq[8][64];
    __shared__ int sidx[160];
    int tid = threadIdx.x;
    int pt0 = blockIdx.x * 8;
    int o0  = blockIdx.y * 64;
    int brow = (pt0 / NPT) * NPT;
    if (tid < 160) sidx[tid] = idx[(size_t)(pt0 + tid/20)*KNN + tid%20];
    __syncthreads();
    int warp = tid >> 5, lane = tid & 31;
    int egsub = lane >> 3, og = lane & 7;
    float acc[5][8] = {};
    int C2 = 2*Cin;
    for (int k0 = 0; k0 < C2; k0 += 16) {
        #pragma unroll
        for (int l = tid; l < 64*16; l += 256) {
            int r = l >> 4, c = l & 15;
            int cc = k0 + c;
            Bs[c][r] = (cc < C2) ? W[(size_t)(o0 + r)*C2 + cc] : 0.f;
        }
        #pragma unroll
        for (int l = tid; l < 160*16; l += 256) {
            int r = l >> 4, c = l & 15;
            int cc = k0 + c;
            int p = r / 20;
            float v = 0.f;
            if (cc < Cin) {
                int m = sidx[r];
                v = __fsub_rn(X[(size_t)(brow + m)*ld + cc], X[(size_t)(pt0 + p)*ld + cc]);
            } else if (cc < C2) {
                v = X[(size_t)(pt0 + p)*ld + (cc - Cin)];
            }
            As[c][r] = v;
        }
        __syncthreads();
        #pragma unroll
        for (int kk = 0; kk < 16; kk++) {
            float a[5];
            #pragma unroll
            for (int i = 0; i < 5; i++) a[i] = As[kk][warp*20 + egsub*5 + i];
            float4 b0 = *(const float4*)&Bs[kk][og*8];
            float4 b1 = *(const float4*)&Bs[kk][og*8 + 4];
            float bv[8] = {b0.x,b0.y,b0.z,b0.w,b1.x,b1.y,b1.z,b1.w};
            #pragma unroll
            for (int i = 0; i < 5; i++)
                #pragma unroll
                for (int j = 0; j < 8; j++)
                    acc[i][j] = __fmaf_rn(a[i], bv[j], acc[i][j]);
        }
        __syncthreads();
    }
    // per-thread stats over its 5 edges
    float mx[8], mn[8]; double s[8], q[8];
    #pragma unroll
    for (int j = 0; j < 8; j++) {
        float y0 = acc[0][j];
        mx[j] = y0; mn[j] = y0;
        s[j] = (double)y0; q[j] = (double)y0*(double)y0;
        #pragma unroll
        for (int i = 1; i < 5; i++) {
            float y = acc[i][j];
            mx[j] = fmaxf(mx[j], y); mn[j] = fminf(mn[j], y);
            s[j] += (double)y; q[j] += (double)y*(double)y;
        }
    }
    // reduce over egsub (lanes l, l^8, l^16, l^24)
    #pragma unroll
    for (int j = 0; j < 8; j++) {
        #pragma unroll
        for (int off = 8; off <= 16; off <<= 1) {
            mx[j] = fmaxf(mx[j], __shfl_xor_sync(0xffffffff, mx[j], off));
            mn[j] = fminf(mn[j], __shfl_xor_sync(0xffffffff, mn[j], off));
            s[j] += __shfl_xor_sync(0xffffffff, s[j], off);
            q[j] += __shfl_xor_sync(0xffffffff, q[j], off);
        }
    }
    if (lane < 8) {       // egsub==0, og=lane
        int pt = pt0 + warp;
        *(float4*)&ymax[(size_t)pt*Cout + o0 + og*8]
            = make_float4(mx[0], mx[1], mx[2], mx[3]);
        *(float4*)&ymax[(size_t)pt*Cout + o0 + og*8 + 4]
            = make_float4(mx[4], mx[5], mx[6], mx[7]);
        *(float4*)&ymin[(size_t)pt*Cout + o0 + og*8]
            = make_float4(mn[0], mn[1], mn[2], mn[3]);
        *(float4*)&ymin[(size_t)pt*Cout + o0 + og*8 + 4]
            = make_float4(mn[4], mn[5], mn[6], mn[7]);
        #pragma unroll
        for (int j = 0; j < 8; j++) {
            rs_sum[warp][og*8 + j] = s[j];
            rs_sq [warp][og*8 + j] = q[j];
        }
    }
    __syncthreads();
    if (tid < 64) {
        double S = 0.0, Q = 0.0;
        #pragma unroll
        for (int w = 0; w < 8; w++) { S += rs_sum[w][tid]; Q += rs_sq[w][tid]; }
        atomicAdd(&chanSum[o0 + tid], S);
        atomicAdd(&chanSqs[o0 + tid], Q);
    }
}

// ------------------------- L4 factorized gather -----------------------------
#define PPB 16
__global__ void gather_kernel(const float* __restrict__ PQ,
                              const int* __restrict__ idx,
                              float* __restrict__ ymax, float* __restrict__ ymin,
                              double* __restrict__ chanSum, double* __restrict__ chanSqs) {
    int o = threadIdx.x;                 // 256 = Cout
    int base = blockIdx.x * PPB;
    __shared__ int sidx[PPB][KNN];
    for (int l = o; l < PPB*KNN; l += 256)
        sidx[l/KNN][l%KNN] = idx[(size_t)(base + l/KNN)*KNN + l%KNN];
    __syncthreads();
    double s = 0.0, q = 0.0;
    for (int p = 0; p < PPB; p++) {
        int pt = base + p;
        int brow = (pt >> 10) << 10;
        float Qv = PQ[(size_t)pt*512 + 256 + o];
        float mx = -FLTMAX, mn = FLTMAX;
        #pragma unroll
        for (int k = 0; k < KNN; k++) {
            float y = __fadd_rn(PQ[(size_t)(brow + sidx[p][k])*512 + o], Qv);
            mx = fmaxf(mx, y); mn = fminf(mn, y);
            double yd = (double)y;
            s += yd; q += yd*yd;
        }
        ymax[(size_t)pt*256 + o] = mx;
        ymin[(size_t)pt*256 + o] = mn;
    }
    atomicAdd(&chanSum[o], s);
    atomicAdd(&chanSqs[o], q);
}

// out = lrelu(((v - m)*rs)*w + b), v = ymax if w>=0 else ymin — exact ref op order
__global__ void apply_edge_kernel(const float* __restrict__ ymax,
                                  const float* __restrict__ ymin,
                                  const float* __restrict__ M,
                                  const float* __restrict__ RS,
                                  const float* __restrict__ bw,
                                  const float* __restrict__ bb,
                                  int Cout, float* __restrict__ out, int ldo) {
    int o  = threadIdx.x;
    int pt = blockIdx.x;
    float w = bw[o];
    float v = (w >= 0.f) ? ymax[(size_t)pt*Cout + o] : ymin[(size_t)pt*Cout + o];
    float t = __fsub_rn(v, M[o]);
    t = __fmul_rn(t, RS[o]);
    t = __fmul_rn(t, w);
    t = __fadd_rn(t, bb[o]);
    out[(size_t)pt*ldo + o] = (t >= 0.f) ? t : __fmul_rn(NEG, t);
}

// ------------------------- conv5 stats + pooled reduce ----------------------
__global__ void y5stats_kernel(const float* __restrict__ Y5,
                               double* __restrict__ chanSum, double* __restrict__ chanSqs) {
    int cg = blockIdx.x * 64;
    int rg = blockIdx.y * 256;
    int t = threadIdx.x; int c = t % 64, ph = t / 64;
    double s = 0.0, sq = 0.0;
    for (int r = ph; r < 256; r += 4) {
        double v = (double)Y5[(size_t)(rg + r)*1024 + cg + c];
        s += v; sq += v*v;
    }
    __shared__ double ss[256], qq[256];
    ss[t] = s; qq[t] = sq; __syncthreads();
    if (ph == 0) {
        s  = ss[c] + ss[c+64] + ss[c+128] + ss[c+192];
        sq = qq[c] + qq[c+64] + qq[c+128] + qq[c+192];
        atomicAdd(&chanSum[cg+c], s);
        atomicAdd(&chanSqs[cg+c], sq);
    }
}

__global__ void y5reduce_kernel(const float* __restrict__ Y5,
                                const float* __restrict__ M, const float* __restrict__ RS,
                                const float* __restrict__ bw, const float* __restrict__ bb,
                                float* __restrict__ feat) {
    int cg = blockIdx.x * 64; int b = blockIdx.y;
    int t = threadIdx.x; int c = t % 64, ph = t / 64;
    float m = M[cg+c], rs = RS[cg+c], w = bw[cg+c], bbv = bb[cg+c];
    float mx = -FLTMAX, s = 0.f;
    for (int n = ph; n < NPT; n += 4) {
        float v = Y5[((size_t)b*NPT + n)*1024 + cg + c];
        float tv = __fsub_rn(v, m);
        tv = __fmul_rn(tv, rs);
        tv = __fmul_rn(tv, w);
        tv = __fadd_rn(tv, bbv);
        tv = (tv >= 0.f) ? tv : __fmul_rn(NEG, tv);
        mx = fmaxf(mx, tv); s += tv;
    }
    __shared__ float sm[256], ssum[256];
    sm[t] = mx; ssum[t] = s; __syncthreads();
    if (ph == 0) {
        mx = fmaxf(fmaxf(sm[c], sm[c+64]), fmaxf(sm[c+128], sm[c+192]));
        s  = ssum[c] + ssum[c+64] + ssum[c+128] + ssum[c+192];
        feat[(size_t)b*2048 + cg + c]        = mx;
        feat[(size_t)b*2048 + 1024 + cg + c] = __fdiv_rn(s, 1024.f);
    }
}

// ------------------------- head: linear + BN(batch=8) + lrelu ---------------
__global__ void head_kernel(const float* __restrict__ in, int Cin,
                            const float* __restrict__ W, const float* __restrict__ bias,
                            const float* __restrict__ bw, const float* __restrict__ bb,
                            float* __restrict__ out, int Cout) {
    int o = blockIdx.x;
    int t = threadIdx.x;
    float acc[8] = {0,0,0,0,0,0,0,0};
    for (int c = t; c < Cin; c += 256) {
        float w = W[(size_t)o*Cin + c];
        #pragma unroll
        for (int b = 0; b < 8; b++) acc[b] = __fmaf_rn(w, in[(size_t)b*Cin + c], acc[b]);
    }
    #pragma unroll
    for (int b = 0; b < 8; b++)
        #pragma unroll
        for (int off = 16; off > 0; off >>= 1)
            acc[b] += __shfl_xor_sync(0xffffffff, acc[b], off);
    __shared__ float ws[8][8];
    int warp = t >> 5, lane = t & 31;
    if (lane == 0)
        #pragma unroll
        for (int b = 0; b < 8; b++) ws[warp][b] = acc[b];
    __syncthreads();
    if (t == 0) {
        float z[8];
        #pragma unroll
        for (int b = 0; b < 8; b++) {
            float s = bias[o];
            #pragma unroll
            for (int w = 0; w < 8; w++) s += ws[w][b];
            z[b] = s;
        }
        float m = 0.f;
        #pragma unroll
        for (int b = 0; b < 8; b++) m += z[b];
        m *= 0.125f;
        float v = 0.f;
        #pragma unroll
        for (int b = 0; b < 8; b++) { float d = __fsub_rn(z[b], m); v = __fmaf_rn(d, d, v); }
        v *= 0.125f;
        float rs = rsqrtf(__fadd_rn(v, EPSB));
        #pragma unroll
        for (int b = 0; b < 8; b++) {
            float tt = __fsub_rn(z[b], m);
            tt = __fmul_rn(tt, rs);
            tt = __fmul_rn(tt, bw[o]);
            tt = __fadd_rn(tt, bb[o]);
            out[(size_t)b*Cout + o] = (tt >= 0.f) ? tt : __fmul_rn(NEG, tt);
        }
    }
}

__global__ void final_kernel(const float* __restrict__ H2, const float* __restrict__ W,
                             const float* __restrict__ bias, float* __restrict__ out) {
    int i = blockIdx.x * blockDim.x + threadIdx.x;
    if (i < 8*40) {
        int b = i / 40, o = i % 40;
        float s = bias[o];
        for (int c = 0; c < 256; c++)
            s = __fmaf_rn(H2[(size_t)b*256 + c], W[(size_t)o*256 + c], s);
        out[i] = s;
    }
}

// ------------------------- host driver --------------------------------------
extern "C" void kernel_launch(void* const* d_in, const int* in_sizes, int n_in,
                              void* d_out, int out_size) {
    const float* x   = (const float*)d_in[0];
    const float* c1w = (const float*)d_in[1];
    const float* c2w = (const float*)d_in[2];
    const float* c3w = (const float*)d_in[3];
    const float* c4w = (const float*)d_in[4];
    const float* c5w = (const float*)d_in[5];
    const float* bnw_[5] = { (const float*)d_in[6], (const float*)d_in[8],
                             (const float*)d_in[10], (const float*)d_in[12],
                             (const float*)d_in[14] };
    const float* bnb_[5] = { (const float*)d_in[7], (const float*)d_in[9],
                             (const float*)d_in[11], (const float*)d_in[13],
                             (const float*)d_in[15] };
    const float* b6w = (const float*)d_in[16];
    const float* b6b = (const float*)d_in[17];
    const float* b7w = (const float*)d_in[18];
    const float* b7b = (const float*)d_in[19];
    const float* l1w = (const float*)d_in[20];
    const float* l1b = (const float*)d_in[21];
    const float* l2w = (const float*)d_in[22];
    const float* l2b = (const float*)d_in[23];
    const float* l3w = (const float*)d_in[24];
    const float* l3b = (const float*)d_in[25];

    float *X0,*XX,*PD,*YMX,*YMN,*CAT,*Y5,*WC,*PQ,*M,*RS,*FEAT,*H1,*H2;
    double *SUM,*SQS;
    int *IDX;
    cudaGetSymbolAddress((void**)&X0,  g_X0);
    cudaGetSymbolAddress((void**)&XX,  g_XX);
    cudaGetSymbolAddress((void**)&PD,  g_PD);
    cudaGetSymbolAddress((void**)&IDX, g_IDX);
    cudaGetSymbolAddress((void**)&YMX, g_YMX);
    cudaGetSymbolAddress((void**)&YMN, g_YMN);
    cudaGetSymbolAddress((void**)&CAT, g_CAT);
    cudaGetSymbolAddress((void**)&Y5,  g_Y5);
    cudaGetSymbolAddress((void**)&WC,  g_WC);
    cudaGetSymbolAddress((void**)&PQ,  g_PQ);
    cudaGetSymbolAddress((void**)&SUM, g_SUM);
    cudaGetSymbolAddress((void**)&SQS, g_SQS);
    cudaGetSymbolAddress((void**)&M,   g_M);
    cudaGetSymbolAddress((void**)&RS,  g_RS);
    cudaGetSymbolAddress((void**)&FEAT,g_FEAT);
    cudaGetSymbolAddress((void**)&H1,  g_H1);
    cudaGetSymbolAddress((void**)&H2,  g_H2);

    transpose_x_kernel<<<(BSZ*NPT*3 + 255)/256, 256>>>(x, X0);

    const float* convW[4] = { c1w, c2w, c3w, c4w };
    int Cin [4] = { 3, 64, 64, 128 };
    int Cout[4] = { 64, 64, 128, 256 };
    int outOff[4] = { 0, 64, 128, 256 };

    for (int L = 0; L < 4; L++) {
        const float* Xin = (L == 0) ? X0 : (CAT + outOff[L-1]);
        int ldin = (L == 0) ? 3 : 512;
        int Ci = Cin[L], Co = Cout[L];

        rownorm_kernel<<<(NPTS_TOT + 255)/256, 256>>>(Xin, ldin, Ci, XX);
        dim3 ggrid(NPT/128, NPT/64, BSZ);
        gram_kernel<<<ggrid, 256>>>(Xin, ldin, Ci, XX, PD);
        topk_kernel<<<(NPTS_TOT*32)/256, 256>>>(PD, IDX);

        zero_stats_kernel<<<4, 256>>>(SUM, SQS);

        if (L < 3) {
            // exact per-edge path: output feeds the next layer's kNN
            dim3 egrid(NPTS_TOT/8, Co/64);
            edgeconv_kernel<<<egrid, 256>>>(Xin, ldin, Ci, Co, convW[L], IDX,
                                            YMX, YMN, SUM, SQS);
        } else {
            // L4 factorized path: no kNN downstream, value-tolerance only
            wcomb_kernel<<<(2*Co*Ci + 255)/256, 256>>>(convW[L], Ci, Co, WC);
            dim3 pqgrid(NPT/128, (2*Co)/64, BSZ);
            gemm_xw_kernel<<<pqgrid, 256>>>(Xin, ldin, Ci, WC, PQ, 2*Co);
            gather_kernel<<<NPTS_TOT/PPB, 256>>>(PQ, IDX, YMX, YMN, SUM, SQS);
        }

        bnfin_kernel<<<(Co + 255)/256, 256>>>(SUM, SQS,
                                              (double)(BSZ*NPT*KNN), Co, M, RS);
        apply_edge_kernel<<<NPTS_TOT, Co>>>(YMX, YMN, M, RS, bnw_[L], bnb_[L],
                                            Co, CAT + outOff[L], 512);
    }

    // conv5: Y5[b,n,o] = CAT[b,n,:] @ c5w[o,:]   (exact fp32, ascending K)
    dim3 g5(NPT/128, 1024/64, BSZ);
    gemm_xw_kernel<<<g5, 256>>>(CAT, 512, 512, c5w, Y5, 1024);
    zero_stats_kernel<<<4, 256>>>(SUM, SQS);
    dim3 sgrid(16, 32);
    y5stats_kernel<<<sgrid, 256>>>(Y5, SUM, SQS);
    bnfin_kernel<<<4, 256>>>(SUM, SQS, (double)(BSZ*NPT), 1024, M, RS);
    dim3 rgrid(16, BSZ);
    y5reduce_kernel<<<rgrid, 256>>>(Y5, M, RS, bnw_[4], bnb_[4], FEAT);

    head_kernel<<<512, 256>>>(FEAT, 2048, l1w, l1b, b6w, b6b, H1, 512);
    head_kernel<<<256, 256>>>(H1,   512,  l2w, l2b, b7w, b7b, H2, 256);
    final_kernel<<<2, 256>>>(H2, l3w, l3b, (float*)d_out);
}

// round 7
// speedup vs baseline: 1.0401x; 1.0401x over previous
#include <cuda_runtime.h>
#include <cstdint>

#define BSZ 8
#define NPT 1024
#define KNN 20
#define NEG 0.2f
#define EPSB 1e-5f
#define NPTS_TOT (BSZ*NPT)
#define FLTMAX 3.402823466e38f

// ------------------------- scratch (device globals; no allocs) -------------
__device__ float  g_X0 [BSZ*NPT*3];
__device__ float  g_XX [BSZ*NPT];
__device__ int    g_IDX[BSZ*NPT*KNN];
__device__ float  g_YMX[BSZ*NPT*256];
__device__ float  g_YMN[BSZ*NPT*256];
__device__ float  g_CAT[BSZ*NPT*512];        // x1|x2|x3|x4 per point row
__device__ float  g_Y5 [BSZ*NPT*1024];       // 32 MB conv5 output
__device__ float  g_WC [512*128];            // L4 combined [W1; W2-W1]
__device__ float  g_PQ [BSZ*NPT*512];        // L4 [P | Q] per point (16 MB)
__device__ double g_SUM[1024];
__device__ double g_SQS[1024];
__device__ float  g_M  [1024];
__device__ float  g_RS [1024];
__device__ float  g_FEAT[BSZ*2048];
__device__ float  g_H1 [BSZ*512];
__device__ float  g_H2 [BSZ*256];

// ------------------------- small utility kernels ---------------------------
__global__ void transpose_x_kernel(const float* __restrict__ x, float* __restrict__ X0) {
    int i = blockIdx.x * blockDim.x + threadIdx.x;
    if (i < BSZ*NPT*3) {
        int b = i / (NPT*3); int rest = i % (NPT*3);
        int n = rest / 3, c = rest % 3;
        X0[i] = x[((size_t)b*3 + c)*NPT + n];
    }
}

// xx[n] = sum_c x[n,c]^2  — square rounded, then ascending adds (NO fma)
__global__ void rownorm_kernel(const float* __restrict__ X, int ld, int Cin,
                               float* __restrict__ xx) {
    int pt = blockIdx.x * blockDim.x + threadIdx.x;
    if (pt < NPTS_TOT) {
        const float* r = X + (size_t)pt * ld;
        float s = 0.f;
        for (int c = 0; c < Cin; c++) {
            float v = r[c];
            s = __fadd_rn(s, __fmul_rn(v, v));
        }
        xx[pt] = s;
    }
}

__global__ void zero_stats_kernel(double* a, double* b) {
    int i = blockIdx.x * blockDim.x + threadIdx.x;
    if (i < 1024) { a[i] = 0.0; b[i] = 0.0; }
}

// L4 combined weights: WC[o] = W1[o]; WC[Cout+o] = W2[o]-W1[o]
__global__ void wcomb_kernel(const float* __restrict__ W, int Cin, int Cout,
                             float* __restrict__ WC) {
    int i = blockIdx.x * blockDim.x + threadIdx.x;
    if (i < 2*Cout*Cin) {
        int o = i / Cin, c = i % Cin;
        if (o < Cout) WC[i] = W[(size_t)o*(2*Cin) + c];
        else {
            int oo = o - Cout;
            WC[i] = __fsub_rn(W[(size_t)oo*(2*Cin) + Cin + c],
                              W[(size_t)oo*(2*Cin) + c]);
        }
    }
}

// From fp64 sums: m = fp32(mean); v = two-pass-style variance; rs = rsqrtf(v+eps)
__global__ void bnfin_kernel(const double* __restrict__ sum, const double* __restrict__ sqs,
                             double cnt, int C,
                             float* __restrict__ M, float* __restrict__ RS) {
    int o = blockIdx.x * blockDim.x + threadIdx.x;
    if (o < C) {
        double mu = sum[o] / cnt;
        float m = (float)mu;
        double vd = sqs[o]/cnt - 2.0*(double)m*mu + (double)m*(double)m;
        float v = (float)vd;
        M[o]  = m;
        RS[o] = rsqrtf(__fadd_rn(v, EPSB));
    }
}

// ------------------------- tiled fp32 GEMM (R5: 64x64, 256 thr, 4x4) -------
// C[b,i,j] = sum_c X[b,i,c]*W[j,c], ascending-K single-accumulator fma chain.
__global__ void gemm_xw_kernel(const float* __restrict__ X, int ldx, int Cin,
                               const float* __restrict__ W,
                               float* __restrict__ out, int ldo) {
    int b  = blockIdx.z;
    int i0 = blockIdx.x * 64;
    int j0 = blockIdx.y * 64;
    __shared__ float As[16][68];
    __shared__ float Bs[16][68];
    int tid = threadIdx.x, tx = tid % 16, ty = tid / 16;
    float acc[4][4] = {};
    const float* Xb = X + (size_t)b * NPT * ldx;
    for (int k0 = 0; k0 < Cin; k0 += 16) {
        for (int l = tid; l < 64*16; l += 256) {
            int r = l >> 4, c = l & 15; int kk = k0 + c;
            As[c][r] = (kk < Cin) ? Xb[(size_t)(i0 + r)*ldx + kk] : 0.f;
            Bs[c][r] = (kk < Cin) ? W [(size_t)(j0 + r)*Cin + kk] : 0.f;
        }
        __syncthreads();
        #pragma unroll
        for (int kk = 0; kk < 16; kk++) {
            float a[4], bv[4];
            #pragma unroll
            for (int i = 0; i < 4; i++) a[i]  = As[kk][ty*4 + i];
            #pragma unroll
            for (int j = 0; j < 4; j++) bv[j] = Bs[kk][tx*4 + j];
            #pragma unroll
            for (int i = 0; i < 4; i++)
                #pragma unroll
                for (int j = 0; j < 4; j++)
                    acc[i][j] = __fmaf_rn(a[i], bv[j], acc[i][j]);
        }
        __syncthreads();
    }
    float* outb = out + (size_t)b * NPT * ldo;
    #pragma unroll
    for (int i = 0; i < 4; i++)
        #pragma unroll
        for (int j = 0; j < 4; j++)
            outb[(size_t)(i0 + ty*4 + i)*ldo + (j0 + tx*4 + j)] = acc[i][j];
}

// ------------------------- FUSED gram + top-k --------------------------------
// Block: 256 thr = 8 warps; warp owns 2 rows. Lane accumulates cols 32j+lane.
// dot over k ascending, single fma accumulator  -> bit-identical to old gram.
// pd = (-xx[col] - (-2*dot)) - xx[row], then jax.lax.top_k semantics.
__device__ __forceinline__ void warp_topk20(float* v, int lane, int* __restrict__ outp) {
    for (int k = 0; k < KNN; k++) {
        float bm = v[0]; int bj = 0;
        #pragma unroll
        for (int j = 1; j < 32; j++)
            if (v[j] > bm) { bm = v[j]; bj = j; }
        float wv = bm;
        int   wm = lane + (bj << 5);
        #pragma unroll
        for (int off = 16; off > 0; off >>= 1) {
            float ov = __shfl_xor_sync(0xffffffff, wv, off);
            int   om = __shfl_xor_sync(0xffffffff, wm, off);
            if (ov > wv || (ov == wv && om < wm)) { wv = ov; wm = om; }
        }
        if (lane == 0) outp[k] = wm;
        if ((wm & 31) == lane) {
            int jj = wm >> 5;
            #pragma unroll
            for (int j = 0; j < 32; j++)
                if (j == jj) v[j] = -FLTMAX;
        }
    }
}

__global__ void __launch_bounds__(256, 2)
gramtopk_kernel(const float* __restrict__ X, int ldx, int Cin,
                const float* __restrict__ xx, int* __restrict__ idxout) {
    __shared__ float As[16][132];      // 16 rows x Cin (float4-readable)
    __shared__ float Bt[32][129];      // k-major col tile, conflict-free
    __shared__ float xxs[1024];
    int tid  = threadIdx.x;
    int warp = tid >> 5, lane = tid & 31;
    int r0   = blockIdx.x * 16;        // 16 rows per block, aligned in batch
    int brow = (r0 >> 10) << 10;
    int rof  = r0 - brow;

    for (int l = tid; l < 16*132; l += 256) {
        int r = l / 132, c = l % 132;
        As[r][c] = (c < Cin) ? X[(size_t)(r0 + r)*ldx + c] : 0.f;
    }
    for (int l = tid; l < 1024; l += 256) xxs[l] = xx[brow + l];
    __syncthreads();

    float xr0 = xxs[rof + warp*2];
    float xr1 = xxs[rof + warp*2 + 1];

    float v0[32], v1[32];
    #pragma unroll
    for (int j = 0; j < 32; j++) { v0[j] = 0.f; v1[j] = 0.f; }

    int nkt = (Cin + 31) >> 5;
    #pragma unroll
    for (int ct = 0; ct < 8; ct++) {
        for (int kt = 0; kt < nkt; kt++) {
            int k0 = kt << 5;
            int kcnt = Cin - k0; if (kcnt > 32) kcnt = 32;
            __syncthreads();           // previous Bt consumers done
            // load Bt[k][col]: warp w -> cols w, w+8, ..; lane = k (coalesced LDG)
            #pragma unroll
            for (int i = 0; i < 16; i++) {
                int col = warp + (i << 3);
                if (lane < kcnt)
                    Bt[lane][col] = X[(size_t)(brow + ct*128 + col)*ldx + k0 + lane];
            }
            __syncthreads();
            if (kcnt == 32) {
                #pragma unroll
                for (int k4 = 0; k4 < 8; k4++) {
                    float4 a0q = *(const float4*)&As[warp*2][k0 + k4*4];
                    float4 a1q = *(const float4*)&As[warp*2 + 1][k0 + k4*4];
                    float a0[4] = {a0q.x, a0q.y, a0q.z, a0q.w};
                    float a1[4] = {a1q.x, a1q.y, a1q.z, a1q.w};
                    #pragma unroll
                    for (int kk = 0; kk < 4; kk++) {
                        int k = k4*4 + kk;
                        #pragma unroll
                        for (int s = 0; s < 4; s++) {
                            float bv = Bt[k][s*32 + lane];
                            v0[ct*4+s] = __fmaf_rn(a0[kk], bv, v0[ct*4+s]);
                            v1[ct*4+s] = __fmaf_rn(a1[kk], bv, v1[ct*4+s]);
                        }
                    }
                }
            } else {
                for (int k = 0; k < kcnt; k++) {
                    float a0 = As[warp*2][k0 + k];
                    float a1 = As[warp*2 + 1][k0 + k];
                    #pragma unroll
                    for (int s = 0; s < 4; s++) {
                        float bv = Bt[k][s*32 + lane];
                        v0[ct*4+s] = __fmaf_rn(a0, bv, v0[ct*4+s]);
                        v1[ct*4+s] = __fmaf_rn(a1, bv, v1[ct*4+s]);
                    }
                }
            }
        }
    }

    // pd transform — exact op order of the old gram epilogue
    #pragma unroll
    for (int j = 0; j < 32; j++) {
        int col = (j << 5) + lane;
        float xj = xxs[col];
        float in0 = __fmul_rn(-2.f, v0[j]);
        v0[j] = __fsub_rn(__fsub_rn(-xj, in0), xr0);
        float in1 = __fmul_rn(-2.f, v1[j]);
        v1[j] = __fsub_rn(__fsub_rn(-xj, in1), xr1);
    }

    int row0 = r0 + warp*2;
    warp_topk20(v0, lane, idxout + (size_t)row0 * KNN);
    warp_topk20(v1, lane, idxout + (size_t)(row0 + 1) * KNN);
}

// ------------------------- per-edge EXACT fp32 EdgeConv (L1-L3, R5) ---------
__global__ void edgeconv_kernel(const float* __restrict__ X, int ld, int Cin, int Cout,
                                const float* __restrict__ W,
                                const int* __restrict__ idx,
                                float* __restrict__ ymax, float* __restrict__ ymin,
                                double* __restrict__ chanSum, double* __restrict__ chanSqs) {
    __shared__ float  As[16][81];
    __shared__ float  Bs[16][66];
    __shared__ float  rmax[16][64], rmin[16][64];
    __shared__ double rsumd[16][64], rsqd[16][64];
    __shared__ int sidx[80];
    int tid = threadIdx.x;
    int pt0 = blockIdx.x * 4;
    int o0  = blockIdx.y * 64;
    int brow = (pt0 / NPT) * NPT;
    if (tid < 80) sidx[tid] = idx[(size_t)(pt0 + tid/20)*KNN + tid%20];
    __syncthreads();
    int eg = tid >> 3;          // 0..15 (5 edges each, within one point)
    int og = tid & 7;           // 0..7  (8 outs each)
    float acc[5][8] = {};
    int C2 = 2*Cin;
    for (int k0 = 0; k0 < C2; k0 += 16) {
        for (int l = tid; l < 64*16; l += 128) {
            int r = l >> 4, c = l & 15;
            int cc = k0 + c;
            Bs[c][r] = (cc < C2) ? W[(size_t)(o0 + r)*C2 + cc] : 0.f;
        }
        for (int l = tid; l < 80*16; l += 128) {
            int r = l >> 4, c = l & 15;
            int cc = k0 + c;
            int p = r / 20;
            float v = 0.f;
            if (cc < Cin) {
                int m = sidx[r];
                v = __fsub_rn(X[(size_t)(brow + m)*ld + cc], X[(size_t)(pt0 + p)*ld + cc]);
            } else if (cc < C2) {
                v = X[(size_t)(pt0 + p)*ld + (cc - Cin)];
            }
            As[c][r] = v;
        }
        __syncthreads();
        #pragma unroll
        for (int kk = 0; kk < 16; kk++) {
            float a[5], bv[8];
            #pragma unroll
            for (int i = 0; i < 5; i++) a[i] = As[kk][eg*5 + i];
            #pragma unroll
            for (int j = 0; j < 8; j++) bv[j] = Bs[kk][og*8 + j];
            #pragma unroll
            for (int i = 0; i < 5; i++)
                #pragma unroll
                for (int j = 0; j < 8; j++)
                    acc[i][j] = __fmaf_rn(a[i], bv[j], acc[i][j]);
        }
        __syncthreads();
    }
    #pragma unroll
    for (int j = 0; j < 8; j++) {
        float y0 = acc[0][j];
        float mx = y0, mn = y0;
        double s = (double)y0, q = (double)y0*(double)y0;
        #pragma unroll
        for (int i = 1; i < 5; i++) {
            float y = acc[i][j];
            mx = fmaxf(mx, y); mn = fminf(mn, y);
            s += (double)y; q += (double)y*(double)y;
        }
        rmax[eg][og*8+j] = mx; rmin[eg][og*8+j] = mn;
        rsumd[eg][og*8+j] = s; rsqd [eg][og*8+j] = q;
    }
    __syncthreads();
    for (int task = tid; task < 256; task += 128) {
        int p = task >> 6, oj = task & 63;
        float mx = rmax[4*p][oj], mn = rmin[4*p][oj];
        #pragma unroll
        for (int e = 1; e < 4; e++) {
            mx = fmaxf(mx, rmax[4*p+e][oj]);
            mn = fminf(mn, rmin[4*p+e][oj]);
        }
        ymax[(size_t)(pt0+p)*Cout + o0 + oj] = mx;
        ymin[(size_t)(pt0+p)*Cout + o0 + oj] = mn;
    }
    if (tid < 64) {
        double s = 0.0, q = 0.0;
        #pragma unroll
        for (int e = 0; e < 16; e++) { s += rsumd[e][tid]; q += rsqd[e][tid]; }
        atomicAdd(&chanSum[o0+tid], s);
        atomicAdd(&chanSqs[o0+tid], q);
    }
}

// ------------------------- L4 factorized gather -----------------------------
#define PPB 16
__global__ void gather_kernel(const float* __restrict__ PQ,
                              const int* __restrict__ idx,
                              float* __restrict__ ymax, float* __restrict__ ymin,
                              double* __restrict__ chanSum, double* __restrict__ chanSqs) {
    int o = threadIdx.x;                 // 256 = Cout
    int base = blockIdx.x * PPB;
    __shared__ int sidx[PPB][KNN];
    for (int l = o; l < PPB*KNN; l += 256)
        sidx[l/KNN][l%KNN] = idx[(size_t)(base + l/KNN)*KNN + l%KNN];
    __syncthreads();
    double s = 0.0, q = 0.0;
    for (int p = 0; p < PPB; p++) {
        int pt = base + p;
        int brow = (pt >> 10) << 10;
        float Qv = PQ[(size_t)pt*512 + 256 + o];
        float mx = -FLTMAX, mn = FLTMAX;
        #pragma unroll
        for (int k = 0; k < KNN; k++) {
            float y = __fadd_rn(PQ[(size_t)(brow + sidx[p][k])*512 + o], Qv);
            mx = fmaxf(mx, y); mn = fminf(mn, y);
            double yd = (double)y;
            s += yd; q += yd*yd;
        }
        ymax[(size_t)pt*256 + o] = mx;
        ymin[(size_t)pt*256 + o] = mn;
    }
    atomicAdd(&chanSum[o], s);
    atomicAdd(&chanSqs[o], q);
}

// out = lrelu(((v - m)*rs)*w + b), v = ymax if w>=0 else ymin — exact ref op order
__global__ void apply_edge_kernel(const float* __restrict__ ymax,
                                  const float* __restrict__ ymin,
                                  const float* __restrict__ M,
                                  const float* __restrict__ RS,
                                  const float* __restrict__ bw,
                                  const float* __restrict__ bb,
                                  int Cout, float* __restrict__ out, int ldo) {
    int o  = threadIdx.x;
    int pt = blockIdx.x;
    float w = bw[o];
    float v = (w >= 0.f) ? ymax[(size_t)pt*Cout + o] : ymin[(size_t)pt*Cout + o];
    float t = __fsub_rn(v, M[o]);
    t = __fmul_rn(t, RS[o]);
    t = __fmul_rn(t, w);
    t = __fadd_rn(t, bb[o]);
    out[(size_t)pt*ldo + o] = (t >= 0.f) ? t : __fmul_rn(NEG, t);
}

// ------------------------- conv5 stats + pooled reduce ----------------------
__global__ void y5stats_kernel(const float* __restrict__ Y5,
                               double* __restrict__ chanSum, double* __restrict__ chanSqs) {
    int cg = blockIdx.x * 64;
    int rg = blockIdx.y * 256;
    int t = threadIdx.x; int c = t % 64, ph = t / 64;
    double s = 0.0, sq = 0.0;
    for (int r = ph; r < 256; r += 4) {
        double v = (double)Y5[(size_t)(rg + r)*1024 + cg + c];
        s += v; sq += v*v;
    }
    __shared__ double ss[256], qq[256];
    ss[t] = s; qq[t] = sq; __syncthreads();
    if (ph == 0) {
        s  = ss[c] + ss[c+64] + ss[c+128] + ss[c+192];
        sq = qq[c] + qq[c+64] + qq[c+128] + qq[c+192];
        atomicAdd(&chanSum[cg+c], s);
        atomicAdd(&chanSqs[cg+c], sq);
    }
}

__global__ void y5reduce_kernel(const float* __restrict__ Y5,
                                const float* __restrict__ M, const float* __restrict__ RS,
                                const float* __restrict__ bw, const float* __restrict__ bb,
                                float* __restrict__ feat) {
    int cg = blockIdx.x * 64; int b = blockIdx.y;
    int t = threadIdx.x; int c = t % 64, ph = t / 64;
    float m = M[cg+c], rs = RS[cg+c], w = bw[cg+c], bbv = bb[cg+c];
    float mx = -FLTMAX, s = 0.f;
    for (int n = ph; n < NPT; n += 4) {
        float v = Y5[((size_t)b*NPT + n)*1024 + cg + c];
        float tv = __fsub_rn(v, m);
        tv = __fmul_rn(tv, rs);
        tv = __fmul_rn(tv, w);
        tv = __fadd_rn(tv, bbv);
        tv = (tv >= 0.f) ? tv : __fmul_rn(NEG, tv);
        mx = fmaxf(mx, tv); s += tv;
    }
    __shared__ float sm[256], ssum[256];
    sm[t] = mx; ssum[t] = s; __syncthreads();
    if (ph == 0) {
        mx = fmaxf(fmaxf(sm[c], sm[c+64]), fmaxf(sm[c+128], sm[c+192]));
        s  = ssum[c] + ssum[c+64] + ssum[c+128] + ssum[c+192];
        feat[(size_t)b*2048 + cg + c]        = mx;
        feat[(size_t)b*2048 + 1024 + cg + c] = __fdiv_rn(s, 1024.f);
    }
}

// ------------------------- head: linear + BN(batch=8) + lrelu ---------------
__global__ void head_kernel(const float* __restrict__ in, int Cin,
                            const float* __restrict__ W, const float* __restrict__ bias,
                            const float* __restrict__ bw, const float* __restrict__ bb,
                            float* __restrict__ out, int Cout) {
    int o = blockIdx.x;
    int t = threadIdx.x;
    float acc[8] = {0,0,0,0,0,0,0,0};
    for (int c = t; c < Cin; c += 256) {
        float w = W[(size_t)o*Cin + c];
        #pragma unroll
        for (int b = 0; b < 8; b++) acc[b] = __fmaf_rn(w, in[(size_t)b*Cin + c], acc[b]);
    }
    #pragma unroll
    for (int b = 0; b < 8; b++)
        #pragma unroll
        for (int off = 16; off > 0; off >>= 1)
            acc[b] += __shfl_xor_sync(0xffffffff, acc[b], off);
    __shared__ float ws[8][8];
    int warp = t >> 5, lane = t & 31;
    if (lane == 0)
        #pragma unroll
        for (int b = 0; b < 8; b++) ws[warp][b] = acc[b];
    __syncthreads();
    if (t == 0) {
        float z[8];
        #pragma unroll
        for (int b = 0; b < 8; b++) {
            float s = bias[o];
            #pragma unroll
            for (int w = 0; w < 8; w++) s += ws[w][b];
            z[b] = s;
        }
        float m = 0.f;
        #pragma unroll
        for (int b = 0; b < 8; b++) m += z[b];
        m *= 0.125f;
        float v = 0.f;
        #pragma unroll
        for (int b = 0; b < 8; b++) { float d = __fsub_rn(z[b], m); v = __fmaf_rn(d, d, v); }
        v *= 0.125f;
        float rs = rsqrtf(__fadd_rn(v, EPSB));
        #pragma unroll
        for (int b = 0; b < 8; b++) {
            float tt = __fsub_rn(z[b], m);
            tt = __fmul_rn(tt, rs);
            tt = __fmul_rn(tt, bw[o]);
            tt = __fadd_rn(tt, bb[o]);
            out[(size_t)b*Cout + o] = (tt >= 0.f) ? tt : __fmul_rn(NEG, tt);
        }
    }
}

__global__ void final_kernel(const float* __restrict__ H2, const float* __restrict__ W,
                             const float* __restrict__ bias, float* __restrict__ out) {
    int i = blockIdx.x * blockDim.x + threadIdx.x;
    if (i < 8*40) {
        int b = i / 40, o = i % 40;
        float s = bias[o];
        for (int c = 0; c < 256; c++)
            s = __fmaf_rn(H2[(size_t)b*256 + c], W[(size_t)o*256 + c], s);
        out[i] = s;
    }
}

// ------------------------- host driver --------------------------------------
extern "C" void kernel_launch(void* const* d_in, const int* in_sizes, int n_in,
                              void* d_out, int out_size) {
    const float* x   = (const float*)d_in[0];
    const float* c1w = (const float*)d_in[1];
    const float* c2w = (const float*)d_in[2];
    const float* c3w = (const float*)d_in[3];
    const float* c4w = (const float*)d_in[4];
    const float* c5w = (const float*)d_in[5];
    const float* bnw_[5] = { (const float*)d_in[6], (const float*)d_in[8],
                             (const float*)d_in[10], (const float*)d_in[12],
                             (const float*)d_in[14] };
    const float* bnb_[5] = { (const float*)d_in[7], (const float*)d_in[9],
                             (const float*)d_in[11], (const float*)d_in[13],
                             (const float*)d_in[15] };
    const float* b6w = (const float*)d_in[16];
    const float* b6b = (const float*)d_in[17];
    const float* b7w = (const float*)d_in[18];
    const float* b7b = (const float*)d_in[19];
    const float* l1w = (const float*)d_in[20];
    const float* l1b = (const float*)d_in[21];
    const float* l2w = (const float*)d_in[22];
    const float* l2b = (const float*)d_in[23];
    const float* l3w = (const float*)d_in[24];
    const float* l3b = (const float*)d_in[25];

    float *X0,*XX,*YMX,*YMN,*CAT,*Y5,*WC,*PQ,*M,*RS,*FEAT,*H1,*H2;
    double *SUM,*SQS;
    int *IDX;
    cudaGetSymbolAddress((void**)&X0,  g_X0);
    cudaGetSymbolAddress((void**)&XX,  g_XX);
    cudaGetSymbolAddress((void**)&IDX, g_IDX);
    cudaGetSymbolAddress((void**)&YMX, g_YMX);
    cudaGetSymbolAddress((void**)&YMN, g_YMN);
    cudaGetSymbolAddress((void**)&CAT, g_CAT);
    cudaGetSymbolAddress((void**)&Y5,  g_Y5);
    cudaGetSymbolAddress((void**)&WC,  g_WC);
    cudaGetSymbolAddress((void**)&PQ,  g_PQ);
    cudaGetSymbolAddress((void**)&SUM, g_SUM);
    cudaGetSymbolAddress((void**)&SQS, g_SQS);
    cudaGetSymbolAddress((void**)&M,   g_M);
    cudaGetSymbolAddress((void**)&RS,  g_RS);
    cudaGetSymbolAddress((void**)&FEAT,g_FEAT);
    cudaGetSymbolAddress((void**)&H1,  g_H1);
    cudaGetSymbolAddress((void**)&H2,  g_H2);

    transpose_x_kernel<<<(BSZ*NPT*3 + 255)/256, 256>>>(x, X0);

    const float* convW[4] = { c1w, c2w, c3w, c4w };
    int Cin [4] = { 3, 64, 64, 128 };
    int Cout[4] = { 64, 64, 128, 256 };
    int outOff[4] = { 0, 64, 128, 256 };

    for (int L = 0; L < 4; L++) {
        const float* Xin = (L == 0) ? X0 : (CAT + outOff[L-1]);
        int ldin = (L == 0) ? 3 : 512;
        int Ci = Cin[L], Co = Cout[L];

        rownorm_kernel<<<(NPTS_TOT + 255)/256, 256>>>(Xin, ldin, Ci, XX);
        gramtopk_kernel<<<NPTS_TOT/16, 256>>>(Xin, ldin, Ci, XX, IDX);

        zero_stats_kernel<<<4, 256>>>(SUM, SQS);

        if (L < 3) {
            // exact per-edge path: output feeds the next layer's kNN
            dim3 egrid(NPTS_TOT/4, Co/64);
            edgeconv_kernel<<<egrid, 128>>>(Xin, ldin, Ci, Co, convW[L], IDX,
                                            YMX, YMN, SUM, SQS);
        } else {
            // L4 factorized path: no kNN downstream, value-tolerance only
            wcomb_kernel<<<(2*Co*Ci + 255)/256, 256>>>(convW[L], Ci, Co, WC);
            dim3 pqgrid(NPT/64, (2*Co)/64, BSZ);
            gemm_xw_kernel<<<pqgrid, 256>>>(Xin, ldin, Ci, WC, PQ, 2*Co);
            gather_kernel<<<NPTS_TOT/PPB, 256>>>(PQ, IDX, YMX, YMN, SUM, SQS);
        }

        bnfin_kernel<<<(Co + 255)/256, 256>>>(SUM, SQS,
                                              (double)(BSZ*NPT*KNN), Co, M, RS);
        apply_edge_kernel<<<NPTS_TOT, Co>>>(YMX, YMN, M, RS, bnw_[L], bnb_[L],
                                            Co, CAT + outOff[L], 512);
    }

    // conv5: Y5[b,n,o] = CAT[b,n,:] @ c5w[o,:]   (exact fp32, ascending K)
    dim3 g5(NPT/64, 1024/64, BSZ);
    gemm_xw_kernel<<<g5, 256>>>(CAT, 512, 512, c5w, Y5, 1024);
    zero_stats_kernel<<<4, 256>>>(SUM, SQS);
    dim3 sgrid(16, 32);
    y5stats_kernel<<<sgrid, 256>>>(Y5, SUM, SQS);
    bnfin_kernel<<<4, 256>>>(SUM, SQS, (double)(BSZ*NPT), 1024, M, RS);
    dim3 rgrid(16, BSZ);
    y5reduce_kernel<<<rgrid, 256>>>(Y5, M, RS, bnw_[4], bnb_[4], FEAT);

    head_kernel<<<512, 256>>>(FEAT, 2048, l1w, l1b, b6w, b6b, H1, 512);
    head_kernel<<<256, 256>>>(H1,   512,  l2w, l2b, b7w, b7b, H2, 256);
    final_kernel<<<2, 256>>>(H2, l3w, l3b, (float*)d_out);
}

// round 8
// speedup vs baseline: 1.1471x; 1.1029x over previous
#include <cuda_runtime.h>
#include <cstdint>

#define BSZ 8
#define NPT 1024
#define KNN 20
#define NEG 0.2f
#define EPSB 1e-5f
#define NPTS_TOT (BSZ*NPT)
#define FLTMAX 3.402823466e38f

// ------------------------- scratch (device globals; no allocs) -------------
__device__ float  g_X0 [BSZ*NPT*3];
__device__ float  g_XX [BSZ*NPT];
__device__ float  g_PD [BSZ*NPT*NPT];        // 32 MB pairwise scores
__device__ int    g_IDX[BSZ*NPT*KNN];
__device__ float  g_YMX[BSZ*NPT*256];
__device__ float  g_YMN[BSZ*NPT*256];
__device__ float  g_CAT[BSZ*NPT*512];        // x1|x2|x3|x4 per point row
__device__ float  g_Y5 [BSZ*NPT*1024];       // 32 MB conv5 output
__device__ float  g_WC [512*128];            // L4 combined [W1; W2-W1]
__device__ float  g_PQ [BSZ*NPT*512];        // L4 [P | Q] per point (16 MB)
__device__ double g_SUM[1024];
__device__ double g_SQS[1024];
__device__ float  g_M  [1024];
__device__ float  g_RS [1024];
__device__ float  g_FEAT[BSZ*2048];
__device__ float  g_H1 [BSZ*512];
__device__ float  g_H2 [BSZ*256];

// ------------------------- small utility kernels ---------------------------
__global__ void transpose_x_kernel(const float* __restrict__ x, float* __restrict__ X0) {
    int i = blockIdx.x * blockDim.x + threadIdx.x;
    if (i < BSZ*NPT*3) {
        int b = i / (NPT*3); int rest = i % (NPT*3);
        int n = rest / 3, c = rest % 3;
        X0[i] = x[((size_t)b*3 + c)*NPT + n];
    }
}

// xx[n] = sum_c x[n,c]^2  — square rounded, then ascending adds (NO fma)
__global__ void rownorm_kernel(const float* __restrict__ X, int ld, int Cin,
                               float* __restrict__ xx) {
    int pt = blockIdx.x * blockDim.x + threadIdx.x;
    if (pt < NPTS_TOT) {
        const float* r = X + (size_t)pt * ld;
        float s = 0.f;
        for (int c = 0; c < Cin; c++) {
            float v = r[c];
            s = __fadd_rn(s, __fmul_rn(v, v));
        }
        xx[pt] = s;
    }
}

__global__ void zero_stats_kernel(double* a, double* b) {
    int i = blockIdx.x * blockDim.x + threadIdx.x;
    if (i < 1024) { a[i] = 0.0; b[i] = 0.0; }
}

// L4 combined weights: WC[o] = W1[o]; WC[Cout+o] = W2[o]-W1[o]
__global__ void wcomb_kernel(const float* __restrict__ W, int Cin, int Cout,
                             float* __restrict__ WC) {
    int i = blockIdx.x * blockDim.x + threadIdx.x;
    if (i < 2*Cout*Cin) {
        int o = i / Cin, c = i % Cin;
        if (o < Cout) WC[i] = W[(size_t)o*(2*Cin) + c];
        else {
            int oo = o - Cout;
            WC[i] = __fsub_rn(W[(size_t)oo*(2*Cin) + Cin + c],
                              W[(size_t)oo*(2*Cin) + c]);
        }
    }
}

// From fp64 sums: m = fp32(mean); v = two-pass-style variance; rs = rsqrtf(v+eps)
__global__ void bnfin_kernel(const double* __restrict__ sum, const double* __restrict__ sqs,
                             double cnt, int C,
                             float* __restrict__ M, float* __restrict__ RS) {
    int o = blockIdx.x * blockDim.x + threadIdx.x;
    if (o < C) {
        double mu = sum[o] / cnt;
        float m = (float)mu;
        double vd = sqs[o]/cnt - 2.0*(double)m*mu + (double)m*(double)m;
        float v = (float)vd;
        M[o]  = m;
        RS[o] = rsqrtf(__fadd_rn(v, EPSB));
    }
}

// ------------------------- tiled fp32 GEMM (64x64, 256 thr, 4x4) -----------
// C[b,i,j] = sum_c X[b,i,c]*W[j,c], ascending-K single-accumulator fma chain.
// Vectorized LDS.128 operand reads (identical values/order -> bit-identical).
__global__ void gemm_xw_kernel(const float* __restrict__ X, int ldx, int Cin,
                               const float* __restrict__ W,
                               float* __restrict__ out, int ldo) {
    int b  = blockIdx.z;
    int i0 = blockIdx.x * 64;
    int j0 = blockIdx.y * 64;
    __shared__ float As[16][68];
    __shared__ float Bs[16][68];
    int tid = threadIdx.x, tx = tid % 16, ty = tid / 16;
    float acc[4][4] = {};
    const float* Xb = X + (size_t)b * NPT * ldx;
    for (int k0 = 0; k0 < Cin; k0 += 16) {
        for (int l = tid; l < 64*16; l += 256) {
            int r = l >> 4, c = l & 15; int kk = k0 + c;
            As[c][r] = (kk < Cin) ? Xb[(size_t)(i0 + r)*ldx + kk] : 0.f;
            Bs[c][r] = (kk < Cin) ? W [(size_t)(j0 + r)*Cin + kk] : 0.f;
        }
        __syncthreads();
        #pragma unroll
        for (int kk = 0; kk < 16; kk++) {
            float4 aq = *(const float4*)&As[kk][ty*4];
            float4 bq = *(const float4*)&Bs[kk][tx*4];
            float a[4]  = {aq.x, aq.y, aq.z, aq.w};
            float bv[4] = {bq.x, bq.y, bq.z, bq.w};
            #pragma unroll
            for (int i = 0; i < 4; i++)
                #pragma unroll
                for (int j = 0; j < 4; j++)
                    acc[i][j] = __fmaf_rn(a[i], bv[j], acc[i][j]);
        }
        __syncthreads();
    }
    float* outb = out + (size_t)b * NPT * ldo;
    #pragma unroll
    for (int i = 0; i < 4; i++)
        #pragma unroll
        for (int j = 0; j < 4; j++)
            outb[(size_t)(i0 + ty*4 + i)*ldo + (j0 + tx*4 + j)] = acc[i][j];
}

// pd[b,i,j] = (-xx[j] - (-2*dot_ij)) - xx[i], dot via ascending fma (exact fp32)
__global__ void gram_kernel(const float* __restrict__ X, int ldx, int Cin,
                            const float* __restrict__ xx, float* __restrict__ S) {
    int b  = blockIdx.z;
    int i0 = blockIdx.x * 64;
    int j0 = blockIdx.y * 64;
    __shared__ float As[16][68];
    __shared__ float Bs[16][68];
    int tid = threadIdx.x, tx = tid % 16, ty = tid / 16;
    float acc[4][4] = {};
    const float* Xb = X + (size_t)b * NPT * ldx;
    for (int k0 = 0; k0 < Cin; k0 += 16) {
        for (int l = tid; l < 64*16; l += 256) {
            int r = l >> 4, c = l & 15; int kk = k0 + c;
            As[c][r] = (kk < Cin) ? Xb[(size_t)(i0 + r)*ldx + kk] : 0.f;
            Bs[c][r] = (kk < Cin) ? Xb[(size_t)(j0 + r)*ldx + kk] : 0.f;
        }
        __syncthreads();
        #pragma unroll
        for (int kk = 0; kk < 16; kk++) {
            float4 aq = *(const float4*)&As[kk][ty*4];
            float4 bq = *(const float4*)&Bs[kk][tx*4];
            float a[4]  = {aq.x, aq.y, aq.z, aq.w};
            float bv[4] = {bq.x, bq.y, bq.z, bq.w};
            #pragma unroll
            for (int i = 0; i < 4; i++)
                #pragma unroll
                for (int j = 0; j < 4; j++)
                    acc[i][j] = __fmaf_rn(a[i], bv[j], acc[i][j]);
        }
        __syncthreads();
    }
    float* Sb = S + (size_t)b * NPT * NPT;
    const float* xxb = xx + (size_t)b * NPT;
    #pragma unroll
    for (int i = 0; i < 4; i++) {
        float xi = xxb[i0 + ty*4 + i];
        #pragma unroll
        for (int j = 0; j < 4; j++) {
            float inner = __fmul_rn(-2.f, acc[i][j]);
            float t1 = __fsub_rn(-xxb[j0 + tx*4 + j], inner);
            Sb[(size_t)(i0 + ty*4 + i)*NPT + (j0 + tx*4 + j)] = __fsub_rn(t1, xi);
        }
    }
}

// ------------------------- top-k (warp per row, register-resident) ----------
// jax.lax.top_k semantics: values descending, ties broken by lowest index.
__global__ void topk_kernel(const float* __restrict__ S, int* __restrict__ idxout) {
    int gwarp = (blockIdx.x * blockDim.x + threadIdx.x) >> 5;
    int lane  = threadIdx.x & 31;
    if (gwarp >= NPTS_TOT) return;
    const float* row = S + (size_t)gwarp * NPT;

    float v[32];
    #pragma unroll
    for (int j = 0; j < 32; j++) v[j] = row[lane + (j << 5)];

    int* outp = idxout + (size_t)gwarp * KNN;
    for (int k = 0; k < KNN; k++) {
        float bm = v[0]; int bj = 0;
        #pragma unroll
        for (int j = 1; j < 32; j++)
            if (v[j] > bm) { bm = v[j]; bj = j; }
        float wv = bm;
        int   wm = lane + (bj << 5);
        #pragma unroll
        for (int off = 16; off > 0; off >>= 1) {
            float ov = __shfl_xor_sync(0xffffffff, wv, off);
            int   om = __shfl_xor_sync(0xffffffff, wm, off);
            if (ov > wv || (ov == wv && om < wm)) { wv = ov; wm = om; }
        }
        if (lane == 0) outp[k] = wm;
        if ((wm & 31) == lane) {
            int jj = wm >> 5;
            #pragma unroll
            for (int j = 0; j < 32; j++)
                if (j == jj) v[j] = -FLTMAX;
        }
    }
}

// ------------------------- per-edge EXACT fp32 EdgeConv (L1-L3) -------------
// y[edge,o] = ascending-fma dot of f=[nbr-ctr | ctr] with W[o,:], reducing
// max/min over k and fp64 channel stats on the fly. 80 edges (4 pts) x 64 outs.
// Bs stride 68 (16B-aligned rows) + float4 b-loads: 7 LDS per 40 FMA.
__global__ void edgeconv_kernel(const float* __restrict__ X, int ld, int Cin, int Cout,
                                const float* __restrict__ W,
                                const int* __restrict__ idx,
                                float* __restrict__ ymax, float* __restrict__ ymin,
                                double* __restrict__ chanSum, double* __restrict__ chanSqs) {
    __shared__ float  As[16][81];
    __shared__ float  Bs[16][68];
    __shared__ float  rmax[16][64], rmin[16][64];
    __shared__ double rsumd[16][64], rsqd[16][64];
    __shared__ int sidx[80];
    int tid = threadIdx.x;
    int pt0 = blockIdx.x * 4;
    int o0  = blockIdx.y * 64;
    int brow = (pt0 / NPT) * NPT;
    if (tid < 80) sidx[tid] = idx[(size_t)(pt0 + tid/20)*KNN + tid%20];
    __syncthreads();
    int eg = tid >> 3;          // 0..15 (5 edges each, within one point)
    int og = tid & 7;           // 0..7  (8 outs each)
    float acc[5][8] = {};
    int C2 = 2*Cin;
    for (int k0 = 0; k0 < C2; k0 += 16) {
        for (int l = tid; l < 64*16; l += 128) {
            int r = l >> 4, c = l & 15;
            int cc = k0 + c;
            Bs[c][r] = (cc < C2) ? W[(size_t)(o0 + r)*C2 + cc] : 0.f;
        }
        for (int l = tid; l < 80*16; l += 128) {
            int r = l >> 4, c = l & 15;
            int cc = k0 + c;
            int p = r / 20;
            float v = 0.f;
            if (cc < Cin) {
                int m = sidx[r];
                v = __fsub_rn(X[(size_t)(brow + m)*ld + cc], X[(size_t)(pt0 + p)*ld + cc]);
            } else if (cc < C2) {
                v = X[(size_t)(pt0 + p)*ld + (cc - Cin)];
            }
            As[c][r] = v;
        }
        __syncthreads();
        #pragma unroll
        for (int kk = 0; kk < 16; kk++) {
            float a[5];
            #pragma unroll
            for (int i = 0; i < 5; i++) a[i] = As[kk][eg*5 + i];
            float4 b0 = *(const float4*)&Bs[kk][og*8];
            float4 b1 = *(const float4*)&Bs[kk][og*8 + 4];
            float bv[8] = {b0.x,b0.y,b0.z,b0.w,b1.x,b1.y,b1.z,b1.w};
            #pragma unroll
            for (int i = 0; i < 5; i++)
                #pragma unroll
                for (int j = 0; j < 8; j++)
                    acc[i][j] = __fmaf_rn(a[i], bv[j], acc[i][j]);
        }
        __syncthreads();
    }
    #pragma unroll
    for (int j = 0; j < 8; j++) {
        float y0 = acc[0][j];
        float mx = y0, mn = y0;
        double s = (double)y0, q = (double)y0*(double)y0;
        #pragma unroll
        for (int i = 1; i < 5; i++) {
            float y = acc[i][j];
            mx = fmaxf(mx, y); mn = fminf(mn, y);
            s += (double)y; q += (double)y*(double)y;
        }
        rmax[eg][og*8+j] = mx; rmin[eg][og*8+j] = mn;
        rsumd[eg][og*8+j] = s; rsqd [eg][og*8+j] = q;
    }
    __syncthreads();
    for (int task = tid; task < 256; task += 128) {
        int p = task >> 6, oj = task & 63;
        float mx = rmax[4*p][oj], mn = rmin[4*p][oj];
        #pragma unroll
        for (int e = 1; e < 4; e++) {
            mx = fmaxf(mx, rmax[4*p+e][oj]);
            mn = fminf(mn, rmin[4*p+e][oj]);
        }
        ymax[(size_t)(pt0+p)*Cout + o0 + oj] = mx;
        ymin[(size_t)(pt0+p)*Cout + o0 + oj] = mn;
    }
    if (tid < 64) {
        double s = 0.0, q = 0.0;
        #pragma unroll
        for (int e = 0; e < 16; e++) { s += rsumd[e][tid]; q += rsqd[e][tid]; }
        atomicAdd(&chanSum[o0+tid], s);
        atomicAdd(&chanSqs[o0+tid], q);
    }
}

// ------------------------- L4 factorized gather -----------------------------
#define PPB 16
__global__ void gather_kernel(const float* __restrict__ PQ,
                              const int* __restrict__ idx,
                              float* __restrict__ ymax, float* __restrict__ ymin,
                              double* __restrict__ chanSum, double* __restrict__ chanSqs) {
    int o = threadIdx.x;                 // 256 = Cout
    int base = blockIdx.x * PPB;
    __shared__ int sidx[PPB][KNN];
    for (int l = o; l < PPB*KNN; l += 256)
        sidx[l/KNN][l%KNN] = idx[(size_t)(base + l/KNN)*KNN + l%KNN];
    __syncthreads();
    double s = 0.0, q = 0.0;
    for (int p = 0; p < PPB; p++) {
        int pt = base + p;
        int brow = (pt >> 10) << 10;
        float Qv = PQ[(size_t)pt*512 + 256 + o];
        float mx = -FLTMAX, mn = FLTMAX;
        #pragma unroll
        for (int k = 0; k < KNN; k++) {
            float y = __fadd_rn(PQ[(size_t)(brow + sidx[p][k])*512 + o], Qv);
            mx = fmaxf(mx, y); mn = fminf(mn, y);
            double yd = (double)y;
            s += yd; q += yd*yd;
        }
        ymax[(size_t)pt*256 + o] = mx;
        ymin[(size_t)pt*256 + o] = mn;
    }
    atomicAdd(&chanSum[o], s);
    atomicAdd(&chanSqs[o], q);
}

// out = lrelu(((v - m)*rs)*w + b), v = ymax if w>=0 else ymin — exact ref op order
__global__ void apply_edge_kernel(const float* __restrict__ ymax,
                                  const float* __restrict__ ymin,
                                  const float* __restrict__ M,
                                  const float* __restrict__ RS,
                                  const float* __restrict__ bw,
                                  const float* __restrict__ bb,
                                  int Cout, float* __restrict__ out, int ldo) {
    int o  = threadIdx.x;
    int pt = blockIdx.x;
    float w = bw[o];
    float v = (w >= 0.f) ? ymax[(size_t)pt*Cout + o] : ymin[(size_t)pt*Cout + o];
    float t = __fsub_rn(v, M[o]);
    t = __fmul_rn(t, RS[o]);
    t = __fmul_rn(t, w);
    t = __fadd_rn(t, bb[o]);
    out[(size_t)pt*ldo + o] = (t >= 0.f) ? t : __fmul_rn(NEG, t);
}

// ------------------------- conv5 stats + pooled reduce ----------------------
__global__ void y5stats_kernel(const float* __restrict__ Y5,
                               double* __restrict__ chanSum, double* __restrict__ chanSqs) {
    int cg = blockIdx.x * 64;
    int rg = blockIdx.y * 256;
    int t = threadIdx.x; int c = t % 64, ph = t / 64;
    double s = 0.0, sq = 0.0;
    for (int r = ph; r < 256; r += 4) {
        double v = (double)Y5[(size_t)(rg + r)*1024 + cg + c];
        s += v; sq += v*v;
    }
    __shared__ double ss[256], qq[256];
    ss[t] = s; qq[t] = sq; __syncthreads();
    if (ph == 0) {
        s  = ss[c] + ss[c+64] + ss[c+128] + ss[c+192];
        sq = qq[c] + qq[c+64] + qq[c+128] + qq[c+192];
        atomicAdd(&chanSum[cg+c], s);
        atomicAdd(&chanSqs[cg+c], sq);
    }
}

__global__ void y5reduce_kernel(const float* __restrict__ Y5,
                                const float* __restrict__ M, const float* __restrict__ RS,
                                const float* __restrict__ bw, const float* __restrict__ bb,
                                float* __restrict__ feat) {
    int cg = blockIdx.x * 64; int b = blockIdx.y;
    int t = threadIdx.x; int c = t % 64, ph = t / 64;
    float m = M[cg+c], rs = RS[cg+c], w = bw[cg+c], bbv = bb[cg+c];
    float mx = -FLTMAX, s = 0.f;
    for (int n = ph; n < NPT; n += 4) {
        float v = Y5[((size_t)b*NPT + n)*1024 + cg + c];
        float tv = __fsub_rn(v, m);
        tv = __fmul_rn(tv, rs);
        tv = __fmul_rn(tv, w);
        tv = __fadd_rn(tv, bbv);
        tv = (tv >= 0.f) ? tv : __fmul_rn(NEG, tv);
        mx = fmaxf(mx, tv); s += tv;
    }
    __shared__ float sm[256], ssum[256];
    sm[t] = mx; ssum[t] = s; __syncthreads();
    if (ph == 0) {
        mx = fmaxf(fmaxf(sm[c], sm[c+64]), fmaxf(sm[c+128], sm[c+192]));
        s  = ssum[c] + ssum[c+64] + ssum[c+128] + ssum[c+192];
        feat[(size_t)b*2048 + cg + c]        = mx;
        feat[(size_t)b*2048 + 1024 + cg + c] = __fdiv_rn(s, 1024.f);
    }
}

// ------------------------- head: linear + BN(batch=8) + lrelu ---------------
__global__ void head_kernel(const float* __restrict__ in, int Cin,
                            const float* __restrict__ W, const float* __restrict__ bias,
                            const float* __restrict__ bw, const float* __restrict__ bb,
                            float* __restrict__ out, int Cout) {
    int o = blockIdx.x;
    int t = threadIdx.x;
    float acc[8] = {0,0,0,0,0,0,0,0};
    for (int c = t; c < Cin; c += 256) {
        float w = W[(size_t)o*Cin + c];
        #pragma unroll
        for (int b = 0; b < 8; b++) acc[b] = __fmaf_rn(w, in[(size_t)b*Cin + c], acc[b]);
    }
    #pragma unroll
    for (int b = 0; b < 8; b++)
        #pragma unroll
        for (int off = 16; off > 0; off >>= 1)
            acc[b] += __shfl_xor_sync(0xffffffff, acc[b], off);
    __shared__ float ws[8][8];
    int warp = t >> 5, lane = t & 31;
    if (lane == 0)
        #pragma unroll
        for (int b = 0; b < 8; b++) ws[warp][b] = acc[b];
    __syncthreads();
    if (t == 0) {
        float z[8];
        #pragma unroll
        for (int b = 0; b < 8; b++) {
            float s = bias[o];
            #pragma unroll
            for (int w = 0; w < 8; w++) s += ws[w][b];
            z[b] = s;
        }
        float m = 0.f;
        #pragma unroll
        for (int b = 0; b < 8; b++) m += z[b];
        m *= 0.125f;
        float v = 0.f;
        #pragma unroll
        for (int b = 0; b < 8; b++) { float d = __fsub_rn(z[b], m); v = __fmaf_rn(d, d, v); }
        v *= 0.125f;
        float rs = rsqrtf(__fadd_rn(v, EPSB));
        #pragma unroll
        for (int b = 0; b < 8; b++) {
            float tt = __fsub_rn(z[b], m);
            tt = __fmul_rn(tt, rs);
            tt = __fmul_rn(tt, bw[o]);
            tt = __fadd_rn(tt, bb[o]);
            out[(size_t)b*Cout + o] = (tt >= 0.f) ? tt : __fmul_rn(NEG, tt);
        }
    }
}

__global__ void final_kernel(const float* __restrict__ H2, const float* __restrict__ W,
                             const float* __restrict__ bias, float* __restrict__ out) {
    int i = blockIdx.x * blockDim.x + threadIdx.x;
    if (i < 8*40) {
        int b = i / 40, o = i % 40;
        float s = bias[o];
        for (int c = 0; c < 256; c++)
            s = __fmaf_rn(H2[(size_t)b*256 + c], W[(size_t)o*256 + c], s);
        out[i] = s;
    }
}

// ------------------------- host driver --------------------------------------
extern "C" void kernel_launch(void* const* d_in, const int* in_sizes, int n_in,
                              void* d_out, int out_size) {
    const float* x   = (const float*)d_in[0];
    const float* c1w = (const float*)d_in[1];
    const float* c2w = (const float*)d_in[2];
    const float* c3w = (const float*)d_in[3];
    const float* c4w = (const float*)d_in[4];
    const float* c5w = (const float*)d_in[5];
    const float* bnw_[5] = { (const float*)d_in[6], (const float*)d_in[8],
                             (const float*)d_in[10], (const float*)d_in[12],
                             (const float*)d_in[14] };
    const float* bnb_[5] = { (const float*)d_in[7], (const float*)d_in[9],
                             (const float*)d_in[11], (const float*)d_in[13],
                             (const float*)d_in[15] };
    const float* b6w = (const float*)d_in[16];
    const float* b6b = (const float*)d_in[17];
    const float* b7w = (const float*)d_in[18];
    const float* b7b = (const float*)d_in[19];
    const float* l1w = (const float*)d_in[20];
    const float* l1b = (const float*)d_in[21];
    const float* l2w = (const float*)d_in[22];
    const float* l2b = (const float*)d_in[23];
    const float* l3w = (const float*)d_in[24];
    const float* l3b = (const float*)d_in[25];

    float *X0,*XX,*PD,*YMX,*YMN,*CAT,*Y5,*WC,*PQ,*M,*RS,*FEAT,*H1,*H2;
    double *SUM,*SQS;
    int *IDX;
    cudaGetSymbolAddress((void**)&X0,  g_X0);
    cudaGetSymbolAddress((void**)&XX,  g_XX);
    cudaGetSymbolAddress((void**)&PD,  g_PD);
    cudaGetSymbolAddress((void**)&IDX, g_IDX);
    cudaGetSymbolAddress((void**)&YMX, g_YMX);
    cudaGetSymbolAddress((void**)&YMN, g_YMN);
    cudaGetSymbolAddress((void**)&CAT, g_CAT);
    cudaGetSymbolAddress((void**)&Y5,  g_Y5);
    cudaGetSymbolAddress((void**)&WC,  g_WC);
    cudaGetSymbolAddress((void**)&PQ,  g_PQ);
    cudaGetSymbolAddress((void**)&SUM, g_SUM);
    cudaGetSymbolAddress((void**)&SQS, g_SQS);
    cudaGetSymbolAddress((void**)&M,   g_M);
    cudaGetSymbolAddress((void**)&RS,  g_RS);
    cudaGetSymbolAddress((void**)&FEAT,g_FEAT);
    cudaGetSymbolAddress((void**)&H1,  g_H1);
    cudaGetSymbolAddress((void**)&H2,  g_H2);

    transpose_x_kernel<<<(BSZ*NPT*3 + 255)/256, 256>>>(x, X0);

    const float* convW[4] = { c1w, c2w, c3w, c4w };
    int Cin [4] = { 3, 64, 64, 128 };
    int Cout[4] = { 64, 64, 128, 256 };
    int outOff[4] = { 0, 64, 128, 256 };

    for (int L = 0; L < 4; L++) {
        const float* Xin = (L == 0) ? X0 : (CAT + outOff[L-1]);
        int ldin = (L == 0) ? 3 : 512;
        int Ci = Cin[L], Co = Cout[L];

        rownorm_kernel<<<(NPTS_TOT + 255)/256, 256>>>(Xin, ldin, Ci, XX);
        dim3 ggrid(NPT/64, NPT/64, BSZ);
        gram_kernel<<<ggrid, 256>>>(Xin, ldin, Ci, XX, PD);
        topk_kernel<<<(NPTS_TOT*32)/256, 256>>>(PD, IDX);

        zero_stats_kernel<<<4, 256>>>(SUM, SQS);

        if (L < 3) {
            // exact per-edge path: output feeds the next layer's kNN
            dim3 egrid(NPTS_TOT/4, Co/64);
            edgeconv_kernel<<<egrid, 128>>>(Xin, ldin, Ci, Co, convW[L], IDX,
                                            YMX, YMN, SUM, SQS);
        } else {
            // L4 factorized path: no kNN downstream, value-tolerance only
            wcomb_kernel<<<(2*Co*Ci + 255)/256, 256>>>(convW[L], Ci, Co, WC);
            dim3 pqgrid(NPT/64, (2*Co)/64, BSZ);
            gemm_xw_kernel<<<pqgrid, 256>>>(Xin, ldin, Ci, WC, PQ, 2*Co);
            gather_kernel<<<NPTS_TOT/PPB, 256>>>(PQ, IDX, YMX, YMN, SUM, SQS);
        }

        bnfin_kernel<<<(Co + 255)/256, 256>>>(SUM, SQS,
                                              (double)(BSZ*NPT*KNN), Co, M, RS);
        apply_edge_kernel<<<NPTS_TOT, Co>>>(YMX, YMN, M, RS, bnw_[L], bnb_[L],
                                            Co, CAT + outOff[L], 512);
    }

    // conv5: Y5[b,n,o] = CAT[b,n,:] @ c5w[o,:]   (exact fp32, ascending K)
    dim3 g5(NPT/64, 1024/64, BSZ);
    gemm_xw_kernel<<<g5, 256>>>(CAT, 512, 512, c5w, Y5, 1024);
    zero_stats_kernel<<<4, 256>>>(SUM, SQS);
    dim3 sgrid(16, 32);
    y5stats_kernel<<<sgrid, 256>>>(Y5, SUM, SQS);
    bnfin_kernel<<<4, 256>>>(SUM, SQS, (double)(BSZ*NPT), 1024, M, RS);
    dim3 rgrid(16, BSZ);
    y5reduce_kernel<<<rgrid, 256>>>(Y5, M, RS, bnw_[4], bnb_[4], FEAT);

    head_kernel<<<512, 256>>>(FEAT, 2048, l1w, l1b, b6w, b6b, H1, 512);
    head_kernel<<<256, 256>>>(H1,   512,  l2w, l2b, b7w, b7b, H2, 256);
    final_kernel<<<2, 256>>>(H2, l3w, l3b, (float*)d_out);
}

// round 9
// speedup vs baseline: 1.1884x; 1.0359x over previous
#include <cuda_runtime.h>
#include <cstdint>

#define BSZ 8
#define NPT 1024
#define KNN 20
#define NEG 0.2f
#define EPSB 1e-5f
#define NPTS_TOT (BSZ*NPT)
#define FLTMAX 3.402823466e38f

// ------------------------- scratch (device globals; no allocs) -------------
__device__ float  g_X0 [BSZ*NPT*3];
__device__ float  g_XX [BSZ*NPT];
__device__ float  g_PD [BSZ*NPT*NPT];        // 32 MB pairwise scores
__device__ int    g_IDX[BSZ*NPT*KNN];
__device__ float  g_YMX[BSZ*NPT*256];
__device__ float  g_YMN[BSZ*NPT*256];
__device__ float  g_CAT[BSZ*NPT*512];        // x1|x2|x3|x4 per point row
__device__ float  g_Y5 [BSZ*NPT*1024];       // 32 MB conv5 output
__device__ float  g_WC [512*128];            // L4 combined [W1; W2-W1]
__device__ float  g_PQ [BSZ*NPT*512];        // L4 [P | Q] per point (16 MB)
__device__ double g_SUM[1024];
__device__ double g_SQS[1024];
__device__ float  g_M  [1024];
__device__ float  g_RS [1024];
__device__ float  g_FEAT[BSZ*2048];
__device__ float  g_H1 [BSZ*512];
__device__ float  g_H2 [BSZ*256];

// ------------------------- small utility kernels ---------------------------
__global__ void transpose_x_kernel(const float* __restrict__ x, float* __restrict__ X0) {
    int i = blockIdx.x * blockDim.x + threadIdx.x;
    if (i < BSZ*NPT*3) {
        int b = i / (NPT*3); int rest = i % (NPT*3);
        int n = rest / 3, c = rest % 3;
        X0[i] = x[((size_t)b*3 + c)*NPT + n];
    }
}

// xx[n] = sum_c x[n,c]^2  — square rounded, then ascending adds (NO fma)
__global__ void rownorm_kernel(const float* __restrict__ X, int ld, int Cin,
                               float* __restrict__ xx) {
    int pt = blockIdx.x * blockDim.x + threadIdx.x;
    if (pt < NPTS_TOT) {
        const float* r = X + (size_t)pt * ld;
        float s = 0.f;
        for (int c = 0; c < Cin; c++) {
            float v = r[c];
            s = __fadd_rn(s, __fmul_rn(v, v));
        }
        xx[pt] = s;
    }
}

__global__ void zero_stats_kernel(double* a, double* b) {
    int i = blockIdx.x * blockDim.x + threadIdx.x;
    if (i < 1024) { a[i] = 0.0; b[i] = 0.0; }
}

// L4 combined weights: WC[o] = W1[o]; WC[Cout+o] = W2[o]-W1[o]
__global__ void wcomb_kernel(const float* __restrict__ W, int Cin, int Cout,
                             float* __restrict__ WC) {
    int i = blockIdx.x * blockDim.x + threadIdx.x;
    if (i < 2*Cout*Cin) {
        int o = i / Cin, c = i % Cin;
        if (o < Cout) WC[i] = W[(size_t)o*(2*Cin) + c];
        else {
            int oo = o - Cout;
            WC[i] = __fsub_rn(W[(size_t)oo*(2*Cin) + Cin + c],
                              W[(size_t)oo*(2*Cin) + c]);
        }
    }
}

// From fp64 sums: m = fp32(mean); v = two-pass-style variance; rs = rsqrtf(v+eps)
__global__ void bnfin_kernel(const double* __restrict__ sum, const double* __restrict__ sqs,
                             double cnt, int C,
                             float* __restrict__ M, float* __restrict__ RS) {
    int o = blockIdx.x * blockDim.x + threadIdx.x;
    if (o < C) {
        double mu = sum[o] / cnt;
        float m = (float)mu;
        double vd = sqs[o]/cnt - 2.0*(double)m*mu + (double)m*(double)m;
        float v = (float)vd;
        M[o]  = m;
        RS[o] = rsqrtf(__fadd_rn(v, EPSB));
    }
}

// ------------------------- tiled fp32 GEMM (64x64, 256 thr, 4x4) -----------
// C[b,i,j] = sum_c X[b,i,c]*W[j,c], ascending-K single-accumulator fma chain.
// Double-buffered smem + register prefetch; values/order bit-identical.
__global__ void gemm_xw_kernel(const float* __restrict__ X, int ldx, int Cin,
                               const float* __restrict__ W,
                               float* __restrict__ out, int ldo) {
    int b  = blockIdx.z;
    int i0 = blockIdx.x * 64;
    int j0 = blockIdx.y * 64;
    __shared__ float As[2][16][68];
    __shared__ float Bs[2][16][68];
    int tid = threadIdx.x, tx = tid % 16, ty = tid / 16;
    float acc[4][4] = {};
    const float* Xb = X + (size_t)b * NPT * ldx;
    int T = (Cin + 15) >> 4;
    // preload tile 0
    #pragma unroll
    for (int n = 0; n < 4; n++) {
        int l = tid + 256*n; int r = l >> 4, c = l & 15;
        As[0][c][r] = (c < Cin) ? Xb[(size_t)(i0 + r)*ldx + c] : 0.f;
        Bs[0][c][r] = (c < Cin) ? W [(size_t)(j0 + r)*Cin + c] : 0.f;
    }
    __syncthreads();
    for (int t = 0; t < T; t++) {
        int cur = t & 1, nxt = cur ^ 1;
        float pa[4], pb[4];
        if (t + 1 < T) {
            int k0n = (t + 1) << 4;
            #pragma unroll
            for (int n = 0; n < 4; n++) {
                int l = tid + 256*n; int r = l >> 4, c = l & 15; int kk = k0n + c;
                pa[n] = (kk < Cin) ? Xb[(size_t)(i0 + r)*ldx + kk] : 0.f;
                pb[n] = (kk < Cin) ? W [(size_t)(j0 + r)*Cin + kk] : 0.f;
            }
        }
        #pragma unroll
        for (int kk = 0; kk < 16; kk++) {
            float4 aq = *(const float4*)&As[cur][kk][ty*4];
            float4 bq = *(const float4*)&Bs[cur][kk][tx*4];
            float a[4]  = {aq.x, aq.y, aq.z, aq.w};
            float bv[4] = {bq.x, bq.y, bq.z, bq.w};
            #pragma unroll
            for (int i = 0; i < 4; i++)
                #pragma unroll
                for (int j = 0; j < 4; j++)
                    acc[i][j] = __fmaf_rn(a[i], bv[j], acc[i][j]);
        }
        if (t + 1 < T) {
            #pragma unroll
            for (int n = 0; n < 4; n++) {
                int l = tid + 256*n; int r = l >> 4, c = l & 15;
                As[nxt][c][r] = pa[n];
                Bs[nxt][c][r] = pb[n];
            }
        }
        __syncthreads();
    }
    float* outb = out + (size_t)b * NPT * ldo;
    #pragma unroll
    for (int i = 0; i < 4; i++)
        #pragma unroll
        for (int j = 0; j < 4; j++)
            outb[(size_t)(i0 + ty*4 + i)*ldo + (j0 + tx*4 + j)] = acc[i][j];
}

// pd[b,i,j] = (-xx[j] - (-2*dot_ij)) - xx[i], dot via ascending fma (exact fp32)
__global__ void gram_kernel(const float* __restrict__ X, int ldx, int Cin,
                            const float* __restrict__ xx, float* __restrict__ S) {
    int b  = blockIdx.z;
    int i0 = blockIdx.x * 64;
    int j0 = blockIdx.y * 64;
    __shared__ float As[2][16][68];
    __shared__ float Bs[2][16][68];
    int tid = threadIdx.x, tx = tid % 16, ty = tid / 16;
    float acc[4][4] = {};
    const float* Xb = X + (size_t)b * NPT * ldx;
    int T = (Cin + 15) >> 4;
    #pragma unroll
    for (int n = 0; n < 4; n++) {
        int l = tid + 256*n; int r = l >> 4, c = l & 15;
        As[0][c][r] = (c < Cin) ? Xb[(size_t)(i0 + r)*ldx + c] : 0.f;
        Bs[0][c][r] = (c < Cin) ? Xb[(size_t)(j0 + r)*ldx + c] : 0.f;
    }
    __syncthreads();
    for (int t = 0; t < T; t++) {
        int cur = t & 1, nxt = cur ^ 1;
        float pa[4], pb[4];
        if (t + 1 < T) {
            int k0n = (t + 1) << 4;
            #pragma unroll
            for (int n = 0; n < 4; n++) {
                int l = tid + 256*n; int r = l >> 4, c = l & 15; int kk = k0n + c;
                pa[n] = (kk < Cin) ? Xb[(size_t)(i0 + r)*ldx + kk] : 0.f;
                pb[n] = (kk < Cin) ? Xb[(size_t)(j0 + r)*ldx + kk] : 0.f;
            }
        }
        #pragma unroll
        for (int kk = 0; kk < 16; kk++) {
            float4 aq = *(const float4*)&As[cur][kk][ty*4];
            float4 bq = *(const float4*)&Bs[cur][kk][tx*4];
            float a[4]  = {aq.x, aq.y, aq.z, aq.w};
            float bv[4] = {bq.x, bq.y, bq.z, bq.w};
            #pragma unroll
            for (int i = 0; i < 4; i++)
                #pragma unroll
                for (int j = 0; j < 4; j++)
                    acc[i][j] = __fmaf_rn(a[i], bv[j], acc[i][j]);
        }
        if (t + 1 < T) {
            #pragma unroll
            for (int n = 0; n < 4; n++) {
                int l = tid + 256*n; int r = l >> 4, c = l & 15;
                As[nxt][c][r] = pa[n];
                Bs[nxt][c][r] = pb[n];
            }
        }
        __syncthreads();
    }
    float* Sb = S + (size_t)b * NPT * NPT;
    const float* xxb = xx + (size_t)b * NPT;
    #pragma unroll
    for (int i = 0; i < 4; i++) {
        float xi = xxb[i0 + ty*4 + i];
        #pragma unroll
        for (int j = 0; j < 4; j++) {
            float inner = __fmul_rn(-2.f, acc[i][j]);
            float t1 = __fsub_rn(-xxb[j0 + tx*4 + j], inner);
            Sb[(size_t)(i0 + ty*4 + i)*NPT + (j0 + tx*4 + j)] = __fsub_rn(t1, xi);
        }
    }
}

// ------------------------- top-k (warp per row, register-resident) ----------
// jax.lax.top_k semantics: values descending, ties broken by lowest index.
__global__ void topk_kernel(const float* __restrict__ S, int* __restrict__ idxout) {
    int gwarp = (blockIdx.x * blockDim.x + threadIdx.x) >> 5;
    int lane  = threadIdx.x & 31;
    if (gwarp >= NPTS_TOT) return;
    const float* row = S + (size_t)gwarp * NPT;

    float v[32];
    #pragma unroll
    for (int j = 0; j < 32; j++) v[j] = row[lane + (j << 5)];

    int* outp = idxout + (size_t)gwarp * KNN;
    for (int k = 0; k < KNN; k++) {
        float bm = v[0]; int bj = 0;
        #pragma unroll
        for (int j = 1; j < 32; j++)
            if (v[j] > bm) { bm = v[j]; bj = j; }
        float wv = bm;
        int   wm = lane + (bj << 5);
        #pragma unroll
        for (int off = 16; off > 0; off >>= 1) {
            float ov = __shfl_xor_sync(0xffffffff, wv, off);
            int   om = __shfl_xor_sync(0xffffffff, wm, off);
            if (ov > wv || (ov == wv && om < wm)) { wv = ov; wm = om; }
        }
        if (lane == 0) outp[k] = wm;
        if ((wm & 31) == lane) {
            int jj = wm >> 5;
            #pragma unroll
            for (int j = 0; j < 32; j++)
                if (j == jj) v[j] = -FLTMAX;
        }
    }
}

// ------------------------- per-edge EXACT fp32 EdgeConv (L1-L3) -------------
// y[edge,o] = ascending-fma dot of f=[nbr-ctr | ctr] with W[o,:]. 80 edges
// (4 pts) x 64 outs per block; warp w == point w, so max/min + fp64 stats
// reduce via __shfl_xor(8,16) in-warp. Smem ~14 KB (was ~34 KB) -> occupancy.
__global__ void edgeconv_kernel(const float* __restrict__ X, int ld, int Cin, int Cout,
                                const float* __restrict__ W,
                                const int* __restrict__ idx,
                                float* __restrict__ ymax, float* __restrict__ ymin,
                                double* __restrict__ chanSum, double* __restrict__ chanSqs) {
    __shared__ float  As[16][81];
    __shared__ float  Bs[16][68];
    __shared__ double wsum[4][64], wsq[4][64];
    __shared__ int sidx[80];
    int tid = threadIdx.x;
    int pt0 = blockIdx.x * 4;
    int o0  = blockIdx.y * 64;
    int brow = (pt0 / NPT) * NPT;
    if (tid < 80) sidx[tid] = idx[(size_t)(pt0 + tid/20)*KNN + tid%20];
    __syncthreads();
    int eg = tid >> 3;          // 0..15 (5 edges each; warp w holds eg 4w..4w+3 = point w)
    int og = tid & 7;           // 0..7  (8 outs each)
    int warp = tid >> 5, lane = tid & 31;
    float acc[5][8] = {};
    int C2 = 2*Cin;
    for (int k0 = 0; k0 < C2; k0 += 16) {
        for (int l = tid; l < 64*16; l += 128) {
            int r = l >> 4, c = l & 15;
            int cc = k0 + c;
            Bs[c][r] = (cc < C2) ? W[(size_t)(o0 + r)*C2 + cc] : 0.f;
        }
        for (int l = tid; l < 80*16; l += 128) {
            int r = l >> 4, c = l & 15;
            int cc = k0 + c;
            int p = r / 20;
            float v = 0.f;
            if (cc < Cin) {
                int m = sidx[r];
                v = __fsub_rn(X[(size_t)(brow + m)*ld + cc], X[(size_t)(pt0 + p)*ld + cc]);
            } else if (cc < C2) {
                v = X[(size_t)(pt0 + p)*ld + (cc - Cin)];
            }
            As[c][r] = v;
        }
        __syncthreads();
        #pragma unroll
        for (int kk = 0; kk < 16; kk++) {
            float a[5];
            #pragma unroll
            for (int i = 0; i < 5; i++) a[i] = As[kk][eg*5 + i];
            float4 b0 = *(const float4*)&Bs[kk][og*8];
            float4 b1 = *(const float4*)&Bs[kk][og*8 + 4];
            float bv[8] = {b0.x,b0.y,b0.z,b0.w,b1.x,b1.y,b1.z,b1.w};
            #pragma unroll
            for (int i = 0; i < 5; i++)
                #pragma unroll
                for (int j = 0; j < 8; j++)
                    acc[i][j] = __fmaf_rn(a[i], bv[j], acc[i][j]);
        }
        __syncthreads();
    }
    // per-out stats: thread covers 5 edges; reduce over the 4 eg-subgroups of
    // this warp (= this point) via shuffle; lane<8 holds the final value.
    #pragma unroll
    for (int j = 0; j < 8; j++) {
        float y0 = acc[0][j];
        float mx = y0, mn = y0;
        double s = (double)y0, q = (double)y0*(double)y0;
        #pragma unroll
        for (int i = 1; i < 5; i++) {
            float y = acc[i][j];
            mx = fmaxf(mx, y); mn = fminf(mn, y);
            s += (double)y; q += (double)y*(double)y;
        }
        mx = fmaxf(mx, __shfl_xor_sync(0xffffffff, mx, 8));
        mx = fmaxf(mx, __shfl_xor_sync(0xffffffff, mx, 16));
        mn = fminf(mn, __shfl_xor_sync(0xffffffff, mn, 8));
        mn = fminf(mn, __shfl_xor_sync(0xffffffff, mn, 16));
        s += __shfl_xor_sync(0xffffffff, s, 8);
        s += __shfl_xor_sync(0xffffffff, s, 16);
        q += __shfl_xor_sync(0xffffffff, q, 8);
        q += __shfl_xor_sync(0xffffffff, q, 16);
        if (lane < 8) {
            int oj = lane*8 + j;
            ymax[(size_t)(pt0 + warp)*Cout + o0 + oj] = mx;
            ymin[(size_t)(pt0 + warp)*Cout + o0 + oj] = mn;
            wsum[warp][oj] = s;
            wsq [warp][oj] = q;
        }
    }
    __syncthreads();
    if (tid < 64) {
        double S = wsum[0][tid] + wsum[1][tid] + wsum[2][tid] + wsum[3][tid];
        double Q = wsq [0][tid] + wsq [1][tid] + wsq [2][tid] + wsq [3][tid];
        atomicAdd(&chanSum[o0 + tid], S);
        atomicAdd(&chanSqs[o0 + tid], Q);
    }
}

// ------------------------- L4 factorized gather -----------------------------
#define PPB 16
__global__ void gather_kernel(const float* __restrict__ PQ,
                              const int* __restrict__ idx,
                              float* __restrict__ ymax, float* __restrict__ ymin,
                              double* __restrict__ chanSum, double* __restrict__ chanSqs) {
    int o = threadIdx.x;                 // 256 = Cout
    int base = blockIdx.x * PPB;
    __shared__ int sidx[PPB][KNN];
    for (int l = o; l < PPB*KNN; l += 256)
        sidx[l/KNN][l%KNN] = idx[(size_t)(base + l/KNN)*KNN + l%KNN];
    __syncthreads();
    double s = 0.0, q = 0.0;
    for (int p = 0; p < PPB; p++) {
        int pt = base + p;
        int brow = (pt >> 10) << 10;
        float Qv = PQ[(size_t)pt*512 + 256 + o];
        float mx = -FLTMAX, mn = FLTMAX;
        #pragma unroll
        for (int k = 0; k < KNN; k++) {
            float y = __fadd_rn(PQ[(size_t)(brow + sidx[p][k])*512 + o], Qv);
            mx = fmaxf(mx, y); mn = fminf(mn, y);
            double yd = (double)y;
            s += yd; q += yd*yd;
        }
        ymax[(size_t)pt*256 + o] = mx;
        ymin[(size_t)pt*256 + o] = mn;
    }
    atomicAdd(&chanSum[o], s);
    atomicAdd(&chanSqs[o], q);
}

// out = lrelu(((v - m)*rs)*w + b), v = ymax if w>=0 else ymin — exact ref op order
__global__ void apply_edge_kernel(const float* __restrict__ ymax,
                                  const float* __restrict__ ymin,
                                  const float* __restrict__ M,
                                  const float* __restrict__ RS,
                                  const float* __restrict__ bw,
                                  const float* __restrict__ bb,
                                  int Cout, float* __restrict__ out, int ldo) {
    int o  = threadIdx.x;
    int pt = blockIdx.x;
    float w = bw[o];
    float v = (w >= 0.f) ? ymax[(size_t)pt*Cout + o] : ymin[(size_t)pt*Cout + o];
    float t = __fsub_rn(v, M[o]);
    t = __fmul_rn(t, RS[o]);
    t = __fmul_rn(t, w);
    t = __fadd_rn(t, bb[o]);
    out[(size_t)pt*ldo + o] = (t >= 0.f) ? t : __fmul_rn(NEG, t);
}

// ------------------------- conv5 stats + pooled reduce ----------------------
__global__ void y5stats_kernel(const float* __restrict__ Y5,
                               double* __restrict__ chanSum, double* __restrict__ chanSqs) {
    int cg = blockIdx.x * 64;
    int rg = blockIdx.y * 256;
    int t = threadIdx.x; int c = t % 64, ph = t / 64;
    double s = 0.0, sq = 0.0;
    for (int r = ph; r < 256; r += 4) {
        double v = (double)Y5[(size_t)(rg + r)*1024 + cg + c];
        s += v; sq += v*v;
    }
    __shared__ double ss[256], qq[256];
    ss[t] = s; qq[t] = sq; __syncthreads();
    if (ph == 0) {
        s  = ss[c] + ss[c+64] + ss[c+128] + ss[c+192];
        sq = qq[c] + qq[c+64] + qq[c+128] + qq[c+192];
        atomicAdd(&chanSum[cg+c], s);
        atomicAdd(&chanSqs[cg+c], sq);
    }
}

__global__ void y5reduce_kernel(const float* __restrict__ Y5,
                                const float* __restrict__ M, const float* __restrict__ RS,
                                const float* __restrict__ bw, const float* __restrict__ bb,
                                float* __restrict__ feat) {
    int cg = blockIdx.x * 64; int b = blockIdx.y;
    int t = threadIdx.x; int c = t % 64, ph = t / 64;
    float m = M[cg+c], rs = RS[cg+c], w = bw[cg+c], bbv = bb[cg+c];
    float mx = -FLTMAX, s = 0.f;
    for (int n = ph; n < NPT; n += 4) {
        float v = Y5[((size_t)b*NPT + n)*1024 + cg + c];
        float tv = __fsub_rn(v, m);
        tv = __fmul_rn(tv, rs);
        tv = __fmul_rn(tv, w);
        tv = __fadd_rn(tv, bbv);
        tv = (tv >= 0.f) ? tv : __fmul_rn(NEG, tv);
        mx = fmaxf(mx, tv); s += tv;
    }
    __shared__ float sm[256], ssum[256];
    sm[t] = mx; ssum[t] = s; __syncthreads();
    if (ph == 0) {
        mx = fmaxf(fmaxf(sm[c], sm[c+64]), fmaxf(sm[c+128], sm[c+192]));
        s  = ssum[c] + ssum[c+64] + ssum[c+128] + ssum[c+192];
        feat[(size_t)b*2048 + cg + c]        = mx;
        feat[(size_t)b*2048 + 1024 + cg + c] = __fdiv_rn(s, 1024.f);
    }
}

// ------------------------- head: linear + BN(batch=8) + lrelu ---------------
__global__ void head_kernel(const float* __restrict__ in, int Cin,
                            const float* __restrict__ W, const float* __restrict__ bias,
                            const float* __restrict__ bw, const float* __restrict__ bb,
                            float* __restrict__ out, int Cout) {
    int o = blockIdx.x;
    int t = threadIdx.x;
    float acc[8] = {0,0,0,0,0,0,0,0};
    for (int c = t; c < Cin; c += 256) {
        float w = W[(size_t)o*Cin + c];
        #pragma unroll
        for (int b = 0; b < 8; b++) acc[b] = __fmaf_rn(w, in[(size_t)b*Cin + c], acc[b]);
    }
    #pragma unroll
    for (int b = 0; b < 8; b++)
        #pragma unroll
        for (int off = 16; off > 0; off >>= 1)
            acc[b] += __shfl_xor_sync(0xffffffff, acc[b], off);
    __shared__ float ws[8][8];
    int warp = t >> 5, lane = t & 31;
    if (lane == 0)
        #pragma unroll
        for (int b = 0; b < 8; b++) ws[warp][b] = acc[b];
    __syncthreads();
    if (t == 0) {
        float z[8];
        #pragma unroll
        for (int b = 0; b < 8; b++) {
            float s = bias[o];
            #pragma unroll
            for (int w = 0; w < 8; w++) s += ws[w][b];
            z[b] = s;
        }
        float m = 0.f;
        #pragma unroll
        for (int b = 0; b < 8; b++) m += z[b];
        m *= 0.125f;
        float v = 0.f;
        #pragma unroll
        for (int b = 0; b < 8; b++) { float d = __fsub_rn(z[b], m); v = __fmaf_rn(d, d, v); }
        v *= 0.125f;
        float rs = rsqrtf(__fadd_rn(v, EPSB));
        #pragma unroll
        for (int b = 0; b < 8; b++) {
            float tt = __fsub_rn(z[b], m);
            tt = __fmul_rn(tt, rs);
            tt = __fmul_rn(tt, bw[o]);
            tt = __fadd_rn(tt, bb[o]);
            out[(size_t)b*Cout + o] = (tt >= 0.f) ? tt : __fmul_rn(NEG, tt);
        }
    }
}

__global__ void final_kernel(const float* __restrict__ H2, const float* __restrict__ W,
                             const float* __restrict__ bias, float* __restrict__ out) {
    int i = blockIdx.x * blockDim.x + threadIdx.x;
    if (i < 8*40) {
        int b = i / 40, o = i % 40;
        float s = bias[o];
        for (int c = 0; c < 256; c++)
            s = __fmaf_rn(H2[(size_t)b*256 + c], W[(size_t)o*256 + c], s);
        out[i] = s;
    }
}

// ------------------------- host driver --------------------------------------
extern "C" void kernel_launch(void* const* d_in, const int* in_sizes, int n_in,
                              void* d_out, int out_size) {
    const float* x   = (const float*)d_in[0];
    const float* c1w = (const float*)d_in[1];
    const float* c2w = (const float*)d_in[2];
    const float* c3w = (const float*)d_in[3];
    const float* c4w = (const float*)d_in[4];
    const float* c5w = (const float*)d_in[5];
    const float* bnw_[5] = { (const float*)d_in[6], (const float*)d_in[8],
                             (const float*)d_in[10], (const float*)d_in[12],
                             (const float*)d_in[14] };
    const float* bnb_[5] = { (const float*)d_in[7], (const float*)d_in[9],
                             (const float*)d_in[11], (const float*)d_in[13],
                             (const float*)d_in[15] };
    const float* b6w = (const float*)d_in[16];
    const float* b6b = (const float*)d_in[17];
    const float* b7w = (const float*)d_in[18];
    const float* b7b = (const float*)d_in[19];
    const float* l1w = (const float*)d_in[20];
    const float* l1b = (const float*)d_in[21];
    const float* l2w = (const float*)d_in[22];
    const float* l2b = (const float*)d_in[23];
    const float* l3w = (const float*)d_in[24];
    const float* l3b = (const float*)d_in[25];

    float *X0,*XX,*PD,*YMX,*YMN,*CAT,*Y5,*WC,*PQ,*M,*RS,*FEAT,*H1,*H2;
    double *SUM,*SQS;
    int *IDX;
    cudaGetSymbolAddress((void**)&X0,  g_X0);
    cudaGetSymbolAddress((void**)&XX,  g_XX);
    cudaGetSymbolAddress((void**)&PD,  g_PD);
    cudaGetSymbolAddress((void**)&IDX, g_IDX);
    cudaGetSymbolAddress((void**)&YMX, g_YMX);
    cudaGetSymbolAddress((void**)&YMN, g_YMN);
    cudaGetSymbolAddress((void**)&CAT, g_CAT);
    cudaGetSymbolAddress((void**)&Y5,  g_Y5);
    cudaGetSymbolAddress((void**)&WC,  g_WC);
    cudaGetSymbolAddress((void**)&PQ,  g_PQ);
    cudaGetSymbolAddress((void**)&SUM, g_SUM);
    cudaGetSymbolAddress((void**)&SQS, g_SQS);
    cudaGetSymbolAddress((void**)&M,   g_M);
    cudaGetSymbolAddress((void**)&RS,  g_RS);
    cudaGetSymbolAddress((void**)&FEAT,g_FEAT);
    cudaGetSymbolAddress((void**)&H1,  g_H1);
    cudaGetSymbolAddress((void**)&H2,  g_H2);

    transpose_x_kernel<<<(BSZ*NPT*3 + 255)/256, 256>>>(x, X0);

    const float* convW[4] = { c1w, c2w, c3w, c4w };
    int Cin [4] = { 3, 64, 64, 128 };
    int Cout[4] = { 64, 64, 128, 256 };
    int outOff[4] = { 0, 64, 128, 256 };

    for (int L = 0; L < 4; L++) {
        const float* Xin = (L == 0) ? X0 : (CAT + outOff[L-1]);
        int ldin = (L == 0) ? 3 : 512;
        int Ci = Cin[L], Co = Cout[L];

        rownorm_kernel<<<(NPTS_TOT + 255)/256, 256>>>(Xin, ldin, Ci, XX);
        dim3 ggrid(NPT/64, NPT/64, BSZ);
        gram_kernel<<<ggrid, 256>>>(Xin, ldin, Ci, XX, PD);
        topk_kernel<<<(NPTS_TOT*32)/256, 256>>>(PD, IDX);

        zero_stats_kernel<<<4, 256>>>(SUM, SQS);

        if (L < 3) {
            // exact per-edge path: output feeds the next layer's kNN
            dim3 egrid(NPTS_TOT/4, Co/64);
            edgeconv_kernel<<<egrid, 128>>>(Xin, ldin, Ci, Co, convW[L], IDX,
                                            YMX, YMN, SUM, SQS);
        } else {
            // L4 factorized path: no kNN downstream, value-tolerance only
            wcomb_kernel<<<(2*Co*Ci + 255)/256, 256>>>(convW[L], Ci, Co, WC);
            dim3 pqgrid(NPT/64, (2*Co)/64, BSZ);
            gemm_xw_kernel<<<pqgrid, 256>>>(Xin, ldin, Ci, WC, PQ, 2*Co);
            gather_kernel<<<NPTS_TOT/PPB, 256>>>(PQ, IDX, YMX, YMN, SUM, SQS);
        }

        bnfin_kernel<<<(Co + 255)/256, 256>>>(SUM, SQS,
                                              (double)(BSZ*NPT*KNN), Co, M, RS);
        apply_edge_kernel<<<NPTS_TOT, Co>>>(YMX, YMN, M, RS, bnw_[L], bnb_[L],
                                            Co, CAT + outOff[L], 512);
    }

    // conv5: Y5[b,n,o] = CAT[b,n,:] @ c5w[o,:]   (exact fp32, ascending K)
    dim3 g5(NPT/64, 1024/64, BSZ);
    gemm_xw_kernel<<<g5, 256>>>(CAT, 512, 512, c5w, Y5, 1024);
    zero_stats_kernel<<<4, 256>>>(SUM, SQS);
    dim3 sgrid(16, 32);
    y5stats_kernel<<<sgrid, 256>>>(Y5, SUM, SQS);
    bnfin_kernel<<<4, 256>>>(SUM, SQS, (double)(BSZ*NPT), 1024, M, RS);
    dim3 rgrid(16, BSZ);
    y5reduce_kernel<<<rgrid, 256>>>(Y5, M, RS, bnw_[4], bnb_[4], FEAT);

    head_kernel<<<512, 256>>>(FEAT, 2048, l1w, l1b, b6w, b6b, H1, 512);
    head_kernel<<<256, 256>>>(H1,   512,  l2w, l2b, b7w, b7b, H2, 256);
    final_kernel<<<2, 256>>>(H2, l3w, l3b, (float*)d_out);
}

// round 10
// speedup vs baseline: 1.2766x; 1.0743x over previous
#include <cuda_runtime.h>
#include <cstdint>

#define BSZ 8
#define NPT 1024
#define KNN 20
#define NEG 0.2f
#define EPSB 1e-5f
#define NPTS_TOT (BSZ*NPT)
#define FLTMAX 3.402823466e38f

// ------------------------- scratch (device globals; no allocs) -------------
__device__ float  g_X0 [BSZ*NPT*3];
__device__ float  g_XX [BSZ*NPT];
__device__ float  g_PD [BSZ*NPT*NPT];        // 32 MB pairwise scores
__device__ int    g_IDX[BSZ*NPT*KNN];
__device__ float  g_YMX[BSZ*NPT*256];
__device__ float  g_YMN[BSZ*NPT*256];
__device__ float  g_CAT[BSZ*NPT*512];        // x1|x2|x3|x4 per point row
__device__ float  g_Y5 [BSZ*NPT*1024];       // 32 MB conv5 output
__device__ float  g_WC [512*128];            // L4 combined [W1; W2-W1]
__device__ float  g_PQ [BSZ*NPT*512];        // L4 [P | Q] per point (16 MB)
__device__ double g_SUM[1024];               // zero-init at load; bnfin re-zeroes
__device__ double g_SQS[1024];
__device__ float  g_M  [1024];
__device__ float  g_RS [1024];
__device__ float  g_FEAT[BSZ*2048];
__device__ float  g_H1 [BSZ*512];
__device__ float  g_H2 [BSZ*256];

// ------------------------- small utility kernels ---------------------------
__global__ void transpose_x_kernel(const float* __restrict__ x, float* __restrict__ X0) {
    int i = blockIdx.x * blockDim.x + threadIdx.x;
    if (i < BSZ*NPT*3) {
        int b = i / (NPT*3); int rest = i % (NPT*3);
        int n = rest / 3, c = rest % 3;
        X0[i] = x[((size_t)b*3 + c)*NPT + n];
    }
}

// xx[n] = sum_c x[n,c]^2  — square rounded, then ascending adds (NO fma)
__global__ void rownorm_kernel(const float* __restrict__ X, int ld, int Cin,
                               float* __restrict__ xx) {
    int pt = blockIdx.x * blockDim.x + threadIdx.x;
    if (pt < NPTS_TOT) {
        const float* r = X + (size_t)pt * ld;
        float s = 0.f;
        for (int c = 0; c < Cin; c++) {
            float v = r[c];
            s = __fadd_rn(s, __fmul_rn(v, v));
        }
        xx[pt] = s;
    }
}

// L4 combined weights: WC[o] = W1[o]; WC[Cout+o] = W2[o]-W1[o]
__global__ void wcomb_kernel(const float* __restrict__ W, int Cin, int Cout,
                             float* __restrict__ WC) {
    int i = blockIdx.x * blockDim.x + threadIdx.x;
    if (i < 2*Cout*Cin) {
        int o = i / Cin, c = i % Cin;
        if (o < Cout) WC[i] = W[(size_t)o*(2*Cin) + c];
        else {
            int oo = o - Cout;
            WC[i] = __fsub_rn(W[(size_t)oo*(2*Cin) + Cin + c],
                              W[(size_t)oo*(2*Cin) + c]);
        }
    }
}

// From fp64 sums: m, rs — then RE-ZEROES the stats slots for the next phase.
__global__ void bnfin_kernel(double* __restrict__ sum, double* __restrict__ sqs,
                             double cnt, int C,
                             float* __restrict__ M, float* __restrict__ RS) {
    int o = blockIdx.x * blockDim.x + threadIdx.x;
    if (o < C) {
        double mu = sum[o] / cnt;
        float m = (float)mu;
        double vd = sqs[o]/cnt - 2.0*(double)m*mu + (double)m*(double)m;
        float v = (float)vd;
        M[o]  = m;
        RS[o] = rsqrtf(__fadd_rn(v, EPSB));
        sum[o] = 0.0;
        sqs[o] = 0.0;
    }
}

// ------------------------- tiled fp32 GEMM (128x64, 256 thr, 8x4, dbuf) ----
// C[b,i,j] = sum_c X[b,i,c]*W[j,c], ascending-K single-accumulator fma chain.
__global__ void gemm_xw_kernel(const float* __restrict__ X, int ldx, int Cin,
                               const float* __restrict__ W,
                               float* __restrict__ out, int ldo) {
    int b  = blockIdx.z;
    int i0 = blockIdx.x * 128;
    int j0 = blockIdx.y * 64;
    __shared__ float As[2][16][132];
    __shared__ float Bs[2][16][68];
    int tid = threadIdx.x, tx = tid % 16, ty = tid / 16;
    float acc[8][4] = {};
    const float* Xb = X + (size_t)b * NPT * ldx;
    int T = (Cin + 15) >> 4;
    #pragma unroll
    for (int n = 0; n < 8; n++) {
        int l = tid + 256*n; int r = l >> 4, c = l & 15;
        As[0][c][r] = (c < Cin) ? Xb[(size_t)(i0 + r)*ldx + c] : 0.f;
    }
    #pragma unroll
    for (int n = 0; n < 4; n++) {
        int l = tid + 256*n; int r = l >> 4, c = l & 15;
        Bs[0][c][r] = (c < Cin) ? W[(size_t)(j0 + r)*Cin + c] : 0.f;
    }
    __syncthreads();
    for (int t = 0; t < T; t++) {
        int cur = t & 1, nxt = cur ^ 1;
        float pa[8], pb[4];
        if (t + 1 < T) {
            int k0n = (t + 1) << 4;
            #pragma unroll
            for (int n = 0; n < 8; n++) {
                int l = tid + 256*n; int r = l >> 4, c = l & 15; int kk = k0n + c;
                pa[n] = (kk < Cin) ? Xb[(size_t)(i0 + r)*ldx + kk] : 0.f;
            }
            #pragma unroll
            for (int n = 0; n < 4; n++) {
                int l = tid + 256*n; int r = l >> 4, c = l & 15; int kk = k0n + c;
                pb[n] = (kk < Cin) ? W[(size_t)(j0 + r)*Cin + kk] : 0.f;
            }
        }
        #pragma unroll
        for (int kk = 0; kk < 16; kk++) {
            float4 a0 = *(const float4*)&As[cur][kk][ty*8];
            float4 a1 = *(const float4*)&As[cur][kk][ty*8 + 4];
            float4 bq = *(const float4*)&Bs[cur][kk][tx*4];
            float a[8]  = {a0.x,a0.y,a0.z,a0.w,a1.x,a1.y,a1.z,a1.w};
            float bv[4] = {bq.x, bq.y, bq.z, bq.w};
            #pragma unroll
            for (int i = 0; i < 8; i++)
                #pragma unroll
                for (int j = 0; j < 4; j++)
                    acc[i][j] = __fmaf_rn(a[i], bv[j], acc[i][j]);
        }
        if (t + 1 < T) {
            #pragma unroll
            for (int n = 0; n < 8; n++) {
                int l = tid + 256*n; int r = l >> 4, c = l & 15;
                As[nxt][c][r] = pa[n];
            }
            #pragma unroll
            for (int n = 0; n < 4; n++) {
                int l = tid + 256*n; int r = l >> 4, c = l & 15;
                Bs[nxt][c][r] = pb[n];
            }
        }
        __syncthreads();
    }
    float* outb = out + (size_t)b * NPT * ldo;
    #pragma unroll
    for (int i = 0; i < 8; i++) {
        float4 v = make_float4(acc[i][0], acc[i][1], acc[i][2], acc[i][3]);
        *(float4*)&outb[(size_t)(i0 + ty*8 + i)*ldo + (j0 + tx*4)] = v;
    }
}

// pd[b,i,j] = (-xx[j] - (-2*dot_ij)) - xx[i], dot via ascending fma (exact fp32)
__global__ void gram_kernel(const float* __restrict__ X, int ldx, int Cin,
                            const float* __restrict__ xx, float* __restrict__ S) {
    int b  = blockIdx.z;
    int i0 = blockIdx.x * 128;
    int j0 = blockIdx.y * 64;
    __shared__ float As[2][16][132];
    __shared__ float Bs[2][16][68];
    int tid = threadIdx.x, tx = tid % 16, ty = tid / 16;
    float acc[8][4] = {};
    const float* Xb = X + (size_t)b * NPT * ldx;
    int T = (Cin + 15) >> 4;
    #pragma unroll
    for (int n = 0; n < 8; n++) {
        int l = tid + 256*n; int r = l >> 4, c = l & 15;
        As[0][c][r] = (c < Cin) ? Xb[(size_t)(i0 + r)*ldx + c] : 0.f;
    }
    #pragma unroll
    for (int n = 0; n < 4; n++) {
        int l = tid + 256*n; int r = l >> 4, c = l & 15;
        Bs[0][c][r] = (c < Cin) ? Xb[(size_t)(j0 + r)*ldx + c] : 0.f;
    }
    __syncthreads();
    for (int t = 0; t < T; t++) {
        int cur = t & 1, nxt = cur ^ 1;
        float pa[8], pb[4];
        if (t + 1 < T) {
            int k0n = (t + 1) << 4;
            #pragma unroll
            for (int n = 0; n < 8; n++) {
                int l = tid + 256*n; int r = l >> 4, c = l & 15; int kk = k0n + c;
                pa[n] = (kk < Cin) ? Xb[(size_t)(i0 + r)*ldx + kk] : 0.f;
            }
            #pragma unroll
            for (int n = 0; n < 4; n++) {
                int l = tid + 256*n; int r = l >> 4, c = l & 15; int kk = k0n + c;
                pb[n] = (kk < Cin) ? Xb[(size_t)(j0 + r)*ldx + kk] : 0.f;
            }
        }
        #pragma unroll
        for (int kk = 0; kk < 16; kk++) {
            float4 a0 = *(const float4*)&As[cur][kk][ty*8];
            float4 a1 = *(const float4*)&As[cur][kk][ty*8 + 4];
            float4 bq = *(const float4*)&Bs[cur][kk][tx*4];
            float a[8]  = {a0.x,a0.y,a0.z,a0.w,a1.x,a1.y,a1.z,a1.w};
            float bv[4] = {bq.x, bq.y, bq.z, bq.w};
            #pragma unroll
            for (int i = 0; i < 8; i++)
                #pragma unroll
                for (int j = 0; j < 4; j++)
                    acc[i][j] = __fmaf_rn(a[i], bv[j], acc[i][j]);
        }
        if (t + 1 < T) {
            #pragma unroll
            for (int n = 0; n < 8; n++) {
                int l = tid + 256*n; int r = l >> 4, c = l & 15;
                As[nxt][c][r] = pa[n];
            }
            #pragma unroll
            for (int n = 0; n < 4; n++) {
                int l = tid + 256*n; int r = l >> 4, c = l & 15;
                Bs[nxt][c][r] = pb[n];
            }
        }
        __syncthreads();
    }
    float* Sb = S + (size_t)b * NPT * NPT;
    const float* xxb = xx + (size_t)b * NPT;
    float4 xjq = *(const float4*)&xxb[j0 + tx*4];
    float xjv[4] = {xjq.x, xjq.y, xjq.z, xjq.w};
    #pragma unroll
    for (int i = 0; i < 8; i++) {
        float xi = xxb[i0 + ty*8 + i];
        float e[4];
        #pragma unroll
        for (int j = 0; j < 4; j++) {
            float inner = __fmul_rn(-2.f, acc[i][j]);
            float t1 = __fsub_rn(-xjv[j], inner);
            e[j] = __fsub_rn(t1, xi);
        }
        *(float4*)&Sb[(size_t)(i0 + ty*8 + i)*NPT + (j0 + tx*4)]
            = make_float4(e[0], e[1], e[2], e[3]);
    }
}

// ------------------------- top-k (warp per row, register-resident) ----------
// jax.lax.top_k semantics: values descending, ties broken by lowest index.
// Lane argmax via group-of-4 + tree-of-8 (prefer lower index on ties —
// identical selection to a serial strict-> scan, but ~5x shorter dep chain).
__global__ void topk_kernel(const float* __restrict__ S, int* __restrict__ idxout) {
    int gwarp = (blockIdx.x * blockDim.x + threadIdx.x) >> 5;
    int lane  = threadIdx.x & 31;
    if (gwarp >= NPTS_TOT) return;
    const float* row = S + (size_t)gwarp * NPT;

    float v[32];
    #pragma unroll
    for (int j = 0; j < 32; j++) v[j] = row[lane + (j << 5)];

    int* outp = idxout + (size_t)gwarp * KNN;
    for (int k = 0; k < KNN; k++) {
        // lane-local argmax, smallest-j tie-break, tree-structured
        float gv[8]; int gj[8];
        #pragma unroll
        for (int g = 0; g < 8; g++) {
            float bv_ = v[4*g]; int bj_ = 4*g;
            #pragma unroll
            for (int e = 1; e < 4; e++)
                if (v[4*g + e] > bv_) { bv_ = v[4*g + e]; bj_ = 4*g + e; }
            gv[g] = bv_; gj[g] = bj_;
        }
        #pragma unroll
        for (int st = 1; st < 8; st <<= 1)
            #pragma unroll
            for (int g = 0; g < 8; g += 2*st)
                if (gv[g + st] > gv[g]) { gv[g] = gv[g + st]; gj[g] = gj[g + st]; }
        float wv = gv[0];
        int   wm = lane + (gj[0] << 5);
        // warp argmax: value desc, index asc on ties
        #pragma unroll
        for (int off = 16; off > 0; off >>= 1) {
            float ov = __shfl_xor_sync(0xffffffff, wv, off);
            int   om = __shfl_xor_sync(0xffffffff, wm, off);
            if (ov > wv || (ov == wv && om < wm)) { wv = ov; wm = om; }
        }
        if (lane == 0) outp[k] = wm;
        if ((wm & 31) == lane) {
            int jj = wm >> 5;
            #pragma unroll
            for (int j = 0; j < 32; j++)
                if (j == jj) v[j] = -FLTMAX;
        }
    }
}

// ------------------------- per-edge EXACT fp32 EdgeConv (L1-L3) -------------
__global__ void edgeconv_kernel(const float* __restrict__ X, int ld, int Cin, int Cout,
                                const float* __restrict__ W,
                                const int* __restrict__ idx,
                                float* __restrict__ ymax, float* __restrict__ ymin,
                                double* __restrict__ chanSum, double* __restrict__ chanSqs) {
    __shared__ float  As[16][81];
    __shared__ float  Bs[16][68];
    __shared__ double wsum[4][64], wsq[4][64];
    __shared__ int sidx[80];
    int tid = threadIdx.x;
    int pt0 = blockIdx.x * 4;
    int o0  = blockIdx.y * 64;
    int brow = (pt0 / NPT) * NPT;
    if (tid < 80) sidx[tid] = idx[(size_t)(pt0 + tid/20)*KNN + tid%20];
    __syncthreads();
    int eg = tid >> 3;          // 0..15 (5 edges each; warp w holds eg 4w..4w+3 = point w)
    int og = tid & 7;           // 0..7  (8 outs each)
    int warp = tid >> 5, lane = tid & 31;
    float acc[5][8] = {};
    int C2 = 2*Cin;
    for (int k0 = 0; k0 < C2; k0 += 16) {
        for (int l = tid; l < 64*16; l += 128) {
            int r = l >> 4, c = l & 15;
            int cc = k0 + c;
            Bs[c][r] = (cc < C2) ? W[(size_t)(o0 + r)*C2 + cc] : 0.f;
        }
        for (int l = tid; l < 80*16; l += 128) {
            int r = l >> 4, c = l & 15;
            int cc = k0 + c;
            int p = r / 20;
            float v = 0.f;
            if (cc < Cin) {
                int m = sidx[r];
                v = __fsub_rn(X[(size_t)(brow + m)*ld + cc], X[(size_t)(pt0 + p)*ld + cc]);
            } else if (cc < C2) {
                v = X[(size_t)(pt0 + p)*ld + (cc - Cin)];
            }
            As[c][r] = v;
        }
        __syncthreads();
        #pragma unroll
        for (int kk = 0; kk < 16; kk++) {
            float a[5];
            #pragma unroll
            for (int i = 0; i < 5; i++) a[i] = As[kk][eg*5 + i];
            float4 b0 = *(const float4*)&Bs[kk][og*8];
            float4 b1 = *(const float4*)&Bs[kk][og*8 + 4];
            float bv[8] = {b0.x,b0.y,b0.z,b0.w,b1.x,b1.y,b1.z,b1.w};
            #pragma unroll
            for (int i = 0; i < 5; i++)
                #pragma unroll
                for (int j = 0; j < 8; j++)
                    acc[i][j] = __fmaf_rn(a[i], bv[j], acc[i][j]);
        }
        __syncthreads();
    }
    #pragma unroll
    for (int j = 0; j < 8; j++) {
        float y0 = acc[0][j];
        float mx = y0, mn = y0;
        double s = (double)y0, q = (double)y0*(double)y0;
        #pragma unroll
        for (int i = 1; i < 5; i++) {
            float y = acc[i][j];
            mx = fmaxf(mx, y); mn = fminf(mn, y);
            s += (double)y; q += (double)y*(double)y;
        }
        mx = fmaxf(mx, __shfl_xor_sync(0xffffffff, mx, 8));
        mx = fmaxf(mx, __shfl_xor_sync(0xffffffff, mx, 16));
        mn = fminf(mn, __shfl_xor_sync(0xffffffff, mn, 8));
        mn = fminf(mn, __shfl_xor_sync(0xffffffff, mn, 16));
        s += __shfl_xor_sync(0xffffffff, s, 8);
        s += __shfl_xor_sync(0xffffffff, s, 16);
        q += __shfl_xor_sync(0xffffffff, q, 8);
        q += __shfl_xor_sync(0xffffffff, q, 16);
        if (lane < 8) {
            int oj = lane*8 + j;
            ymax[(size_t)(pt0 + warp)*Cout + o0 + oj] = mx;
            ymin[(size_t)(pt0 + warp)*Cout + o0 + oj] = mn;
            wsum[warp][oj] = s;
            wsq [warp][oj] = q;
        }
    }
    __syncthreads();
    if (tid < 64) {
        double S = wsum[0][tid] + wsum[1][tid] + wsum[2][tid] + wsum[3][tid];
        double Q = wsq [0][tid] + wsq [1][tid] + wsq [2][tid] + wsq [3][tid];
        atomicAdd(&chanSum[o0 + tid], S);
        atomicAdd(&chanSqs[o0 + tid], Q);
    }
}

// ------------------------- L4 factorized gather -----------------------------
#define PPB 16
__global__ void gather_kernel(const float* __restrict__ PQ,
                              const int* __restrict__ idx,
                              float* __restrict__ ymax, float* __restrict__ ymin,
                              double* __restrict__ chanSum, double* __restrict__ chanSqs) {
    int o = threadIdx.x;                 // 256 = Cout
    int base = blockIdx.x * PPB;
    __shared__ int sidx[PPB][KNN];
    for (int l = o; l < PPB*KNN; l += 256)
        sidx[l/KNN][l%KNN] = idx[(size_t)(base + l/KNN)*KNN + l%KNN];
    __syncthreads();
    double s = 0.0, q = 0.0;
    for (int p = 0; p < PPB; p++) {
        int pt = base + p;
        int brow = (pt >> 10) << 10;
        float Qv = PQ[(size_t)pt*512 + 256 + o];
        float mx = -FLTMAX, mn = FLTMAX;
        #pragma unroll
        for (int k = 0; k < KNN; k++) {
            float y = __fadd_rn(PQ[(size_t)(brow + sidx[p][k])*512 + o], Qv);
            mx = fmaxf(mx, y); mn = fminf(mn, y);
            double yd = (double)y;
            s += yd; q += yd*yd;
        }
        ymax[(size_t)pt*256 + o] = mx;
        ymin[(size_t)pt*256 + o] = mn;
    }
    atomicAdd(&chanSum[o], s);
    atomicAdd(&chanSqs[o], q);
}

// out = lrelu(((v - m)*rs)*w + b), v = ymax if w>=0 else ymin — exact ref op order
__global__ void apply_edge_kernel(const float* __restrict__ ymax,
                                  const float* __restrict__ ymin,
                                  const float* __restrict__ M,
                                  const float* __restrict__ RS,
                                  const float* __restrict__ bw,
                                  const float* __restrict__ bb,
                                  int Cout, float* __restrict__ out, int ldo) {
    int o  = threadIdx.x;
    int pt = blockIdx.x;
    float w = bw[o];
    float v = (w >= 0.f) ? ymax[(size_t)pt*Cout + o] : ymin[(size_t)pt*Cout + o];
    float t = __fsub_rn(v, M[o]);
    t = __fmul_rn(t, RS[o]);
    t = __fmul_rn(t, w);
    t = __fadd_rn(t, bb[o]);
    out[(size_t)pt*ldo + o] = (t >= 0.f) ? t : __fmul_rn(NEG, t);
}

// ------------------------- conv5 stats + pooled reduce ----------------------
__global__ void y5stats_kernel(const float* __restrict__ Y5,
                               double* __restrict__ chanSum, double* __restrict__ chanSqs) {
    int cg = blockIdx.x * 64;
    int rg = blockIdx.y * 256;
    int t = threadIdx.x; int c = t % 64, ph = t / 64;
    double s = 0.0, sq = 0.0;
    for (int r = ph; r < 256; r += 4) {
        double v = (double)Y5[(size_t)(rg + r)*1024 + cg + c];
        s += v; sq += v*v;
    }
    __shared__ double ss[256], qq[256];
    ss[t] = s; qq[t] = sq; __syncthreads();
    if (ph == 0) {
        s  = ss[c] + ss[c+64] + ss[c+128] + ss[c+192];
        sq = qq[c] + qq[c+64] + qq[c+128] + qq[c+192];
        atomicAdd(&chanSum[cg+c], s);
        atomicAdd(&chanSqs[cg+c], sq);
    }
}

__global__ void y5reduce_kernel(const float* __restrict__ Y5,
                                const float* __restrict__ M, const float* __restrict__ RS,
                                const float* __restrict__ bw, const float* __restrict__ bb,
                                float* __restrict__ feat) {
    int cg = blockIdx.x * 64; int b = blockIdx.y;
    int t = threadIdx.x; int c = t % 64, ph = t / 64;
    float m = M[cg+c], rs = RS[cg+c], w = bw[cg+c], bbv = bb[cg+c];
    float mx = -FLTMAX, s = 0.f;
    for (int n = ph; n < NPT; n += 4) {
        float v = Y5[((size_t)b*NPT + n)*1024 + cg + c];
        float tv = __fsub_rn(v, m);
        tv = __fmul_rn(tv, rs);
        tv = __fmul_rn(tv, w);
        tv = __fadd_rn(tv, bbv);
        tv = (tv >= 0.f) ? tv : __fmul_rn(NEG, tv);
        mx = fmaxf(mx, tv); s += tv;
    }
    __shared__ float sm[256], ssum[256];
    sm[t] = mx; ssum[t] = s; __syncthreads();
    if (ph == 0) {
        mx = fmaxf(fmaxf(sm[c], sm[c+64]), fmaxf(sm[c+128], sm[c+192]));
        s  = ssum[c] + ssum[c+64] + ssum[c+128] + ssum[c+192];
        feat[(size_t)b*2048 + cg + c]        = mx;
        feat[(size_t)b*2048 + 1024 + cg + c] = __fdiv_rn(s, 1024.f);
    }
}

// ------------------------- head: linear + BN(batch=8) + lrelu ---------------
__global__ void head_kernel(const float* __restrict__ in, int Cin,
                            const float* __restrict__ W, const float* __restrict__ bias,
                            const float* __restrict__ bw, const float* __restrict__ bb,
                            float* __restrict__ out, int Cout) {
    int o = blockIdx.x;
    int t = threadIdx.x;
    float acc[8] = {0,0,0,0,0,0,0,0};
    for (int c = t; c < Cin; c += 256) {
        float w = W[(size_t)o*Cin + c];
        #pragma unroll
        for (int b = 0; b < 8; b++) acc[b] = __fmaf_rn(w, in[(size_t)b*Cin + c], acc[b]);
    }
    #pragma unroll
    for (int b = 0; b < 8; b++)
        #pragma unroll
        for (int off = 16; off > 0; off >>= 1)
            acc[b] += __shfl_xor_sync(0xffffffff, acc[b], off);
    __shared__ float ws[8][8];
    int warp = t >> 5, lane = t & 31;
    if (lane == 0)
        #pragma unroll
        for (int b = 0; b < 8; b++) ws[warp][b] = acc[b];
    __syncthreads();
    if (t == 0) {
        float z[8];
        #pragma unroll
        for (int b = 0; b < 8; b++) {
            float s = bias[o];
            #pragma unroll
            for (int w = 0; w < 8; w++) s += ws[w][b];
            z[b] = s;
        }
        float m = 0.f;
        #pragma unroll
        for (int b = 0; b < 8; b++) m += z[b];
        m *= 0.125f;
        float v = 0.f;
        #pragma unroll
        for (int b = 0; b < 8; b++) { float d = __fsub_rn(z[b], m); v = __fmaf_rn(d, d, v); }
        v *= 0.125f;
        float rs = rsqrtf(__fadd_rn(v, EPSB));
        #pragma unroll
        for (int b = 0; b < 8; b++) {
            float tt = __fsub_rn(z[b], m);
            tt = __fmul_rn(tt, rs);
            tt = __fmul_rn(tt, bw[o]);
            tt = __fadd_rn(tt, bb[o]);
            out[(size_t)b*Cout + o] = (tt >= 0.f) ? tt : __fmul_rn(NEG, tt);
        }
    }
}

__global__ void final_kernel(const float* __restrict__ H2, const float* __restrict__ W,
                             const float* __restrict__ bias, float* __restrict__ out) {
    int i = blockIdx.x * blockDim.x + threadIdx.x;
    if (i < 8*40) {
        int b = i / 40, o = i % 40;
        float s = bias[o];
        for (int c = 0; c < 256; c++)
            s = __fmaf_rn(H2[(size_t)b*256 + c], W[(size_t)o*256 + c], s);
        out[i] = s;
    }
}

// ------------------------- host driver --------------------------------------
extern "C" void kernel_launch(void* const* d_in, const int* in_sizes, int n_in,
                              void* d_out, int out_size) {
    const float* x   = (const float*)d_in[0];
    const float* c1w = (const float*)d_in[1];
    const float* c2w = (const float*)d_in[2];
    const float* c3w = (const float*)d_in[3];
    const float* c4w = (const float*)d_in[4];
    const float* c5w = (const float*)d_in[5];
    const float* bnw_[5] = { (const float*)d_in[6], (const float*)d_in[8],
                             (const float*)d_in[10], (const float*)d_in[12],
                             (const float*)d_in[14] };
    const float* bnb_[5] = { (const float*)d_in[7], (const float*)d_in[9],
                             (const float*)d_in[11], (const float*)d_in[13],
                             (const float*)d_in[15] };
    const float* b6w = (const float*)d_in[16];
    const float* b6b = (const float*)d_in[17];
    const float* b7w = (const float*)d_in[18];
    const float* b7b = (const float*)d_in[19];
    const float* l1w = (const float*)d_in[20];
    const float* l1b = (const float*)d_in[21];
    const float* l2w = (const float*)d_in[22];
    const float* l2b = (const float*)d_in[23];
    const float* l3w = (const float*)d_in[24];
    const float* l3b = (const float*)d_in[25];

    float *X0,*XX,*PD,*YMX,*YMN,*CAT,*Y5,*WC,*PQ,*M,*RS,*FEAT,*H1,*H2;
    double *SUM,*SQS;
    int *IDX;
    cudaGetSymbolAddress((void**)&X0,  g_X0);
    cudaGetSymbolAddress((void**)&XX,  g_XX);
    cudaGetSymbolAddress((void**)&PD,  g_PD);
    cudaGetSymbolAddress((void**)&IDX, g_IDX);
    cudaGetSymbolAddress((void**)&YMX, g_YMX);
    cudaGetSymbolAddress((void**)&YMN, g_YMN);
    cudaGetSymbolAddress((void**)&CAT, g_CAT);
    cudaGetSymbolAddress((void**)&Y5,  g_Y5);
    cudaGetSymbolAddress((void**)&WC,  g_WC);
    cudaGetSymbolAddress((void**)&PQ,  g_PQ);
    cudaGetSymbolAddress((void**)&SUM, g_SUM);
    cudaGetSymbolAddress((void**)&SQS, g_SQS);
    cudaGetSymbolAddress((void**)&M,   g_M);
    cudaGetSymbolAddress((void**)&RS,  g_RS);
    cudaGetSymbolAddress((void**)&FEAT,g_FEAT);
    cudaGetSymbolAddress((void**)&H1,  g_H1);
    cudaGetSymbolAddress((void**)&H2,  g_H2);

    transpose_x_kernel<<<(BSZ*NPT*3 + 255)/256, 256>>>(x, X0);

    const float* convW[4] = { c1w, c2w, c3w, c4w };
    int Cin [4] = { 3, 64, 64, 128 };
    int Cout[4] = { 64, 64, 128, 256 };
    int outOff[4] = { 0, 64, 128, 256 };

    for (int L = 0; L < 4; L++) {
        const float* Xin = (L == 0) ? X0 : (CAT + outOff[L-1]);
        int ldin = (L == 0) ? 3 : 512;
        int Ci = Cin[L], Co = Cout[L];

        rownorm_kernel<<<(NPTS_TOT + 255)/256, 256>>>(Xin, ldin, Ci, XX);
        dim3 ggrid(NPT/128, NPT/64, BSZ);
        gram_kernel<<<ggrid, 256>>>(Xin, ldin, Ci, XX, PD);
        topk_kernel<<<(NPTS_TOT*32)/256, 256>>>(PD, IDX);

        if (L < 3) {
            // exact per-edge path: output feeds the next layer's kNN
            dim3 egrid(NPTS_TOT/4, Co/64);
            edgeconv_kernel<<<egrid, 128>>>(Xin, ldin, Ci, Co, convW[L], IDX,
                                            YMX, YMN, SUM, SQS);
        } else {
            // L4 factorized path: no kNN downstream, value-tolerance only
            wcomb_kernel<<<(2*Co*Ci + 255)/256, 256>>>(convW[L], Ci, Co, WC);
            dim3 pqgrid(NPT/128, (2*Co)/64, BSZ);
            gemm_xw_kernel<<<pqgrid, 256>>>(Xin, ldin, Ci, WC, PQ, 2*Co);
            gather_kernel<<<NPTS_TOT/PPB, 256>>>(PQ, IDX, YMX, YMN, SUM, SQS);
        }

        bnfin_kernel<<<(Co + 255)/256, 256>>>(SUM, SQS,
                                              (double)(BSZ*NPT*KNN), Co, M, RS);
        apply_edge_kernel<<<NPTS_TOT, Co>>>(YMX, YMN, M, RS, bnw_[L], bnb_[L],
                                            Co, CAT + outOff[L], 512);
    }

    // conv5: Y5[b,n,o] = CAT[b,n,:] @ c5w[o,:]   (exact fp32, ascending K)
    dim3 g5(NPT/128, 1024/64, BSZ);
    gemm_xw_kernel<<<g5, 256>>>(CAT, 512, 512, c5w, Y5, 1024);
    dim3 sgrid(16, 32);
    y5stats_kernel<<<sgrid, 256>>>(Y5, SUM, SQS);
    bnfin_kernel<<<4, 256>>>(SUM, SQS, (double)(BSZ*NPT), 1024, M, RS);
    dim3 rgrid(16, BSZ);
    y5reduce_kernel<<<rgrid, 256>>>(Y5, M, RS, bnw_[4], bnb_[4], FEAT);

    head_kernel<<<512, 256>>>(FEAT, 2048, l1w, l1b, b6w, b6b, H1, 512);
    head_kernel<<<256, 256>>>(H1,   512,  l2w, l2b, b7w, b7b, H2, 256);
    final_kernel<<<2, 256>>>(H2, l3w, l3b, (float*)d_out);
}